// round 12
// baseline (speedup 1.0000x reference)
#include <cuda_runtime.h>
#include <cuda_fp16.h>
#include <cstdint>
#include <math.h>

#define NN 100000
#define EE 800000
#define NB_MAX 512

// ---------------- scratch (device globals; no cudaMalloc allowed) ----------------
__device__ int   g_cnt[NN];
__device__ int   g_row[NN + 1];
__device__ int   g_cur[NN];
__device__ int   g_bsum[NB_MAX];
__device__ int   g_csrc[EE];
__device__ float g_h [NN * 128];
__device__ float g_xl[NN * 128];
__device__ float g_xr[NN * 128];
__device__ float g_gg[NN * 128];
__device__ float g_b1cat[128];
__device__ __half g_pk[NN * 256];       // activation pack: [hi(K) | lo(K)] fp16 per row
__device__ __half g_W0[64 * 256];       // layer0 weight image [K x 256] fp16
__device__ __half g_W1[128 * 256];      // layer1
__device__ __half g_W2[128 * 256];      // layer2
__device__ __half g_WH[128 * 128];      // head

// ---------------- mma helpers ----------------
__device__ __forceinline__ void ldsm4(uint32_t addr, uint32_t& r0, uint32_t& r1,
                                      uint32_t& r2, uint32_t& r3) {
    asm volatile("ldmatrix.sync.aligned.m8n8.x4.shared.b16 {%0,%1,%2,%3}, [%4];"
                 : "=r"(r0), "=r"(r1), "=r"(r2), "=r"(r3) : "r"(addr));
}
__device__ __forceinline__ void ldsm4t(uint32_t addr, uint32_t& r0, uint32_t& r1,
                                       uint32_t& r2, uint32_t& r3) {
    asm volatile("ldmatrix.sync.aligned.m8n8.x4.trans.shared.b16 {%0,%1,%2,%3}, [%4];"
                 : "=r"(r0), "=r"(r1), "=r"(r2), "=r"(r3) : "r"(addr));
}
__device__ __forceinline__ void mma_f16(float* c, const uint32_t* a, uint32_t b0, uint32_t b1) {
    asm volatile(
        "mma.sync.aligned.m16n8k16.row.col.f32.f16.f16.f32 "
        "{%0,%1,%2,%3},{%4,%5,%6,%7},{%8,%9},{%0,%1,%2,%3};"
        : "+f"(c[0]), "+f"(c[1]), "+f"(c[2]), "+f"(c[3])
        : "r"(a[0]), "r"(a[1]), "r"(a[2]), "r"(a[3]), "r"(b0), "r"(b1));
}
__device__ __forceinline__ void split4h(float4 v, uint2& hi, uint2& lo) {
    __half h0 = __float2half(v.x), h1 = __float2half(v.y);
    __half h2 = __float2half(v.z), h3 = __float2half(v.w);
    __half l0 = __float2half(v.x - __half2float(h0));
    __half l1 = __float2half(v.y - __half2float(h1));
    __half l2 = __float2half(v.z - __half2float(h2));
    __half l3 = __float2half(v.w - __half2float(h3));
    hi.x = ((uint32_t)__half_as_ushort(h1) << 16) | __half_as_ushort(h0);
    hi.y = ((uint32_t)__half_as_ushort(h3) << 16) | __half_as_ushort(h2);
    lo.x = ((uint32_t)__half_as_ushort(l1) << 16) | __half_as_ushort(l0);
    lo.y = ((uint32_t)__half_as_ushort(l3) << 16) | __half_as_ushort(l2);
}

// ---------------- weight pre-convert: fp32 [K x H] pair -> fp16 image [K x NT] ----------------
template <int K, int NT>
__global__ void k_convW(const float* __restrict__ Wl, const float* __restrict__ Wr,
                        __half* __restrict__ img) {
    int idx = blockIdx.x * blockDim.x + threadIdx.x;
    if (idx >= K * NT) return;
    int k = idx / NT, col = idx % NT;
    const int H = NT / 2;
    float v = (col < H) ? Wl[k * H + col] : Wr[k * H + col - H];
    img[idx] = __float2half(v);
}

__global__ void k_biascat(const float* __restrict__ b1a, const float* __restrict__ b1b) {
    int i = threadIdx.x;
    if (i < 64) { g_b1cat[i] = b1a[i]; g_b1cat[64 + i] = b1b[i]; }
}

// ---------------- HMMA GEMM: 128 rows x 128 cols, merged hi/lo terms, 2 CTAs/SM ----------------
#define APAD 72
#define BPAD 136
template <int K, int NT, bool BIAS_RELU>
__global__ void __launch_bounds__(256, 2) k_gemm_mma(
    const __half* __restrict__ Apack,
    const __half* __restrict__ Wimg,
    float* __restrict__ out1, float* __restrict__ out2,
    const float* __restrict__ bias, int n)
{
    constexpr int CH = K / 64;                    // merged k-chunks (64 wide, hi+lo together)
    constexpr int ABYTES = 128 * APAD * 2;        // 18432 (per A term)
    constexpr int BBYTES = 64 * BPAD * 2;         // 17408
    constexpr int STG = 2 * ABYTES + BBYTES;      // 54272 per stage
    constexpr int K2 = 2 * K;
    extern __shared__ char sm[];
    const uint32_t sbase = (uint32_t)__cvta_generic_to_shared(sm);
    const int tid = threadIdx.x, lane = tid & 31, wid = tid >> 5;
    const int wm = wid & 3, wn = wid >> 2;        // 4 warps M (32 rows), 2 warps N (64 cols)
    const int row0 = blockIdx.x * 128;
    const int col0 = blockIdx.y * 128;            // 128-wide column block within NT

    auto loadChunk = [&](int c) {
        const int a_hi = c * 64;
        const int a_lo = K + c * 64;
        const int brow = c * 64;
        const uint32_t sAh = sbase + (uint32_t)(c & 1) * STG;
        const uint32_t sAl = sAh + ABYTES;
        const uint32_t sB  = sAl + ABYTES;
        #pragma unroll
        for (int i = tid; i < 1024; i += 256) {                 // A-hi: 128 x 64
            int r = i >> 3, cc = (i & 7) * 8;
            int grow = row0 + r; if (grow > n - 1) grow = n - 1;
            uint32_t dst = sAh + (uint32_t)(r * APAD + cc) * 2;
            const __half* src = Apack + (size_t)grow * K2 + a_hi + cc;
            asm volatile("cp.async.ca.shared.global [%0], [%1], 16;" :: "r"(dst), "l"(src));
        }
        #pragma unroll
        for (int i = tid; i < 1024; i += 256) {                 // A-lo: 128 x 64
            int r = i >> 3, cc = (i & 7) * 8;
            int grow = row0 + r; if (grow > n - 1) grow = n - 1;
            uint32_t dst = sAl + (uint32_t)(r * APAD + cc) * 2;
            const __half* src = Apack + (size_t)grow * K2 + a_lo + cc;
            asm volatile("cp.async.ca.shared.global [%0], [%1], 16;" :: "r"(dst), "l"(src));
        }
        #pragma unroll
        for (int i = tid; i < 1024; i += 256) {                 // B: 64 x 128
            int r = i >> 4, cc = (i & 15) * 8;
            uint32_t dst = sB + (uint32_t)(r * BPAD + cc) * 2;
            const __half* src = Wimg + (size_t)(brow + r) * NT + col0 + cc;
            asm volatile("cp.async.ca.shared.global [%0], [%1], 16;" :: "r"(dst), "l"(src));
        }
        asm volatile("cp.async.commit_group;" ::: "memory");
    };

    float acc[2][8][4];
    #pragma unroll
    for (int i = 0; i < 2; i++)
        #pragma unroll
        for (int j = 0; j < 8; j++)
            #pragma unroll
            for (int q = 0; q < 4; q++) acc[i][j][q] = 0.f;

    loadChunk(0);
    if (CH > 1) loadChunk(1);

    for (int c = 0; c < CH; c++) {
        if (c < CH - 1) asm volatile("cp.async.wait_group 1;" ::: "memory");
        else            asm volatile("cp.async.wait_group 0;" ::: "memory");
        __syncthreads();
        if (c + 2 < CH) loadChunk(c + 2);
        const uint32_t sAh = sbase + (uint32_t)(c & 1) * STG;
        const uint32_t sAl = sAh + ABYTES;
        const uint32_t sB  = sAl + ABYTES;
        #pragma unroll
        for (int ks = 0; ks < 4; ks++) {
            uint32_t ah[2][4], al[2][4];
            #pragma unroll
            for (int mi = 0; mi < 2; mi++) {
                uint32_t roff =
                    (uint32_t)((wm * 32 + mi * 16 + (lane & 15)) * APAD + ks * 16 + 8 * (lane >> 4)) * 2;
                ldsm4(sAh + roff, ah[mi][0], ah[mi][1], ah[mi][2], ah[mi][3]);
                ldsm4(sAl + roff, al[mi][0], al[mi][1], al[mi][2], al[mi][3]);
            }
            #pragma unroll
            for (int ng = 0; ng < 4; ng++) {
                uint32_t b0, b1, b2, b3;
                uint32_t addr = sB +
                    (uint32_t)((ks * 16 + (lane & 15)) * BPAD + wn * 64 + ng * 16 + 8 * (lane >> 4)) * 2;
                ldsm4t(addr, b0, b1, b2, b3);
                mma_f16(acc[0][ng * 2],     ah[0], b0, b1);
                mma_f16(acc[0][ng * 2],     al[0], b0, b1);
                mma_f16(acc[0][ng * 2 + 1], ah[0], b2, b3);
                mma_f16(acc[0][ng * 2 + 1], al[0], b2, b3);
                mma_f16(acc[1][ng * 2],     ah[1], b0, b1);
                mma_f16(acc[1][ng * 2],     al[1], b0, b1);
                mma_f16(acc[1][ng * 2 + 1], ah[1], b2, b3);
                mma_f16(acc[1][ng * 2 + 1], al[1], b2, b3);
            }
        }
        if (c < CH - 1) __syncthreads();
    }

    // epilogue
    const int rb = row0 + wm * 32 + (lane >> 2);
    const int cbl = wn * 64 + (lane & 3) * 2;     // col within 128-wide block
    #pragma unroll
    for (int mi = 0; mi < 2; mi++) {
        #pragma unroll
        for (int ni = 0; ni < 8; ni++) {
            int col = col0 + cbl + ni * 8;        // global col within NT
            #pragma unroll
            for (int h = 0; h < 2; h++) {
                int rg = rb + mi * 16 + h * 8;
                if (rg < n) {
                    float2 v;
                    v.x = acc[mi][ni][h * 2 + 0];
                    v.y = acc[mi][ni][h * 2 + 1];
                    if (BIAS_RELU) {
                        v.x = fmaxf(v.x + bias[col], 0.f);
                        v.y = fmaxf(v.y + bias[col + 1], 0.f);
                    }
                    float* dst = out1;
                    int cc = col;
                    if (NT == 256 && col >= 128) { dst = out2; cc = col - 128; }
                    *(float2*)(dst + (size_t)rg * 128 + cc) = v;
                }
            }
        }
    }
}

// ---------------- CSR build ----------------
__global__ void k_zero(int n) {
    int i = blockIdx.x * blockDim.x + threadIdx.x;
    if (i < n) g_cnt[i] = 0;
}

__global__ void k_count(const int* __restrict__ dstv, int e) {
    int i = blockIdx.x * blockDim.x + threadIdx.x;
    if (i < e) atomicAdd(&g_cnt[dstv[i]], 1);
}

__global__ void k_scan_a(int n) {
    __shared__ int sh[256];
    int i = blockIdx.x * 256 + threadIdx.x;
    int v = (i < n) ? g_cnt[i] : 0;
    sh[threadIdx.x] = v;
    __syncthreads();
    #pragma unroll
    for (int o = 1; o < 256; o <<= 1) {
        int t = (threadIdx.x >= o) ? sh[threadIdx.x - o] : 0;
        __syncthreads();
        sh[threadIdx.x] += t;
        __syncthreads();
    }
    if (i < n) g_row[i] = sh[threadIdx.x] - v;
    if (threadIdx.x == 255) g_bsum[blockIdx.x] = sh[255];
}

__global__ void k_scan_b(int nb) {
    __shared__ int sh[NB_MAX];
    int t = threadIdx.x;
    int v = (t < nb) ? g_bsum[t] : 0;
    sh[t] = v;
    __syncthreads();
    #pragma unroll
    for (int o = 1; o < NB_MAX; o <<= 1) {
        int u = (t >= o) ? sh[t - o] : 0;
        __syncthreads();
        sh[t] += u;
        __syncthreads();
    }
    if (t < nb) g_bsum[t] = sh[t] - v;
}

__global__ void k_scan_c(int n, int e) {
    int i = blockIdx.x * 256 + threadIdx.x;
    if (i < n) {
        int r = g_row[i] + g_bsum[blockIdx.x];
        g_row[i] = r;
        g_cur[i] = r;
    }
    if (i == 0) g_row[n] = e;
}

__global__ void k_scatter(const int* __restrict__ srcv, const int* __restrict__ dstv, int e) {
    int i = blockIdx.x * blockDim.x + threadIdx.x;
    if (i < e) {
        int pos = atomicAdd(&g_cur[dstv[i]], 1);
        g_csrc[pos] = srcv[i];
    }
}

__global__ void k_sortcsr(int n) {
    int i = blockIdx.x * blockDim.x + threadIdx.x;
    if (i >= n) return;
    int b = g_row[i], e2 = g_row[i + 1];
    for (int a = b + 1; a < e2; a++) {
        int v = g_csrc[a];
        int k = a;
        while (k > b && g_csrc[k - 1] > v) { g_csrc[k] = g_csrc[k - 1]; k--; }
        g_csrc[k] = v;
    }
}

// ---------------- LayerNorm kernels (write fp16 hi/lo pack for the GEMM) ----------------
__global__ void __launch_bounds__(256) k_ln64(const float* __restrict__ x,
                                              const float* __restrict__ g,
                                              const float* __restrict__ b,
                                              __half* __restrict__ pack, int n) {
    int w = (blockIdx.x * 256 + threadIdx.x) >> 5;
    int lane = threadIdx.x & 31;
    if (w >= n) return;
    float2 v = *(const float2*)(x + (size_t)w * 64 + lane * 2);
    float s = v.x + v.y;
    float q = v.x * v.x + v.y * v.y;
    #pragma unroll
    for (int o = 16; o; o >>= 1) {
        s += __shfl_xor_sync(0xffffffffu, s, o);
        q += __shfl_xor_sync(0xffffffffu, q, o);
    }
    float m  = s * (1.f / 64.f);
    float var = q * (1.f / 64.f) - m * m;
    float rs = rsqrtf(var + 1e-5f);
    float2 gg = *(const float2*)(g + lane * 2);
    float2 bb = *(const float2*)(b + lane * 2);
    float y0 = (v.x - m) * rs * gg.x + bb.x;
    float y1 = (v.y - m) * rs * gg.y + bb.y;
    __half h0 = __float2half(y0), h1 = __float2half(y1);
    __half l0 = __float2half(y0 - __half2float(h0));
    __half l1 = __float2half(y1 - __half2float(h1));
    uint32_t hw = ((uint32_t)__half_as_ushort(h1) << 16) | __half_as_ushort(h0);
    uint32_t lw = ((uint32_t)__half_as_ushort(l1) << 16) | __half_as_ushort(l0);
    *(uint32_t*)(pack + (size_t)w * 128 + lane * 2)      = hw;
    *(uint32_t*)(pack + (size_t)w * 128 + 64 + lane * 2) = lw;
}

__global__ void __launch_bounds__(256) k_ln128(const float* __restrict__ in,
                                               const float* __restrict__ g,
                                               const float* __restrict__ b,
                                               const float* __restrict__ res,
                                               float rscale, int doRelu,
                                               float* __restrict__ outf,
                                               __half* __restrict__ pack, int n) {
    int w = (blockIdx.x * 256 + threadIdx.x) >> 5;
    int lane = threadIdx.x & 31;
    if (w >= n) return;
    int c0 = lane * 4;
    float4 v = *(const float4*)(in + (size_t)w * 128 + c0);
    float s = v.x + v.y + v.z + v.w;
    float q = v.x * v.x + v.y * v.y + v.z * v.z + v.w * v.w;
    #pragma unroll
    for (int o = 16; o; o >>= 1) {
        s += __shfl_xor_sync(0xffffffffu, s, o);
        q += __shfl_xor_sync(0xffffffffu, q, o);
    }
    float m   = s * (1.f / 128.f);
    float var = q * (1.f / 128.f) - m * m;
    float rs  = rsqrtf(var + 1e-5f);
    float4 gg = *(const float4*)(g + c0);
    float4 bb = *(const float4*)(b + c0);
    float4 y;
    y.x = (v.x - m) * rs * gg.x + bb.x;
    y.y = (v.y - m) * rs * gg.y + bb.y;
    y.z = (v.z - m) * rs * gg.z + bb.z;
    y.w = (v.w - m) * rs * gg.w + bb.w;
    if (res) {
        float4 r4 = *(const float4*)(res + (size_t)w * 128 + c0);
        y.x += rscale * r4.x; y.y += rscale * r4.y;
        y.z += rscale * r4.z; y.w += rscale * r4.w;
    }
    if (doRelu) {
        y.x = fmaxf(y.x, 0.f); y.y = fmaxf(y.y, 0.f);
        y.z = fmaxf(y.z, 0.f); y.w = fmaxf(y.w, 0.f);
    }
    if (outf) *(float4*)(outf + (size_t)w * 128 + c0) = y;
    uint2 hi, lo;
    split4h(y, hi, lo);
    *(uint2*)(pack + (size_t)w * 256 + c0)       = hi;
    *(uint2*)(pack + (size_t)w * 256 + 128 + c0) = lo;
}

// ---------------- GATv2 aggregation: warp per dst node, online softmax, 2-edge ILP ----------------
__global__ void __launch_bounds__(256) k_agg(const float* __restrict__ xl,
                                             const float* __restrict__ xr,
                                             const float* __restrict__ att,
                                             float* __restrict__ out, int n, int grp) {
    int w = (blockIdx.x * 256 + threadIdx.x) >> 5;
    int lane = threadIdx.x & 31;
    if (w >= n) return;
    int c0 = lane * 4;
    float4 a4 = *(const float4*)(att + c0);
    float4 r4 = *(const float4*)(xr + (size_t)w * 128 + c0);
    int beg = g_row[w], deg = g_row[w + 1] - beg;
    float m = -1e30f, s = 0.f;
    float4 acc = make_float4(0.f, 0.f, 0.f, 0.f);

    auto logit = [&](float4 x) -> float {
        float e0 = x.x + r4.x, e1 = x.y + r4.y, e2 = x.z + r4.z, e3 = x.w + r4.w;
        e0 = (e0 > 0.f) ? e0 : 0.2f * e0;
        e1 = (e1 > 0.f) ? e1 : 0.2f * e1;
        e2 = (e2 > 0.f) ? e2 : 0.2f * e2;
        e3 = (e3 > 0.f) ? e3 : 0.2f * e3;
        return fmaf(a4.x, e0, fmaf(a4.y, e1, fmaf(a4.z, e2, a4.w * e3)));
    };

    int j = -1;                              // j == -1 is the self-loop
    for (; j + 1 < deg; j += 2) {
        int s0 = (j < 0) ? w : g_csrc[beg + j];
        int s1 = g_csrc[beg + j + 1];
        float4 x0 = *(const float4*)(xl + (size_t)s0 * 128 + c0);
        float4 x1 = *(const float4*)(xl + (size_t)s1 * 128 + c0);
        float p0 = logit(x0);
        float p1 = logit(x1);
        #pragma unroll
        for (int o = 1; o < 32; o <<= 1)
            if (o < grp) {
                p0 += __shfl_xor_sync(0xffffffffu, p0, o);
                p1 += __shfl_xor_sync(0xffffffffu, p1, o);
            }
        float mn = fmaxf(m, fmaxf(p0, p1));
        float sc = __expf(m - mn);
        float w0 = __expf(p0 - mn);
        float w1 = __expf(p1 - mn);
        s = fmaf(s, sc, w0 + w1);
        acc.x = fmaf(acc.x, sc, fmaf(w0, x0.x, w1 * x1.x));
        acc.y = fmaf(acc.y, sc, fmaf(w0, x0.y, w1 * x1.y));
        acc.z = fmaf(acc.z, sc, fmaf(w0, x0.z, w1 * x1.z));
        acc.w = fmaf(acc.w, sc, fmaf(w0, x0.w, w1 * x1.w));
        m = mn;
    }
    if (j < deg) {                           // leftover single edge (or lone self-loop)
        int s0 = (j < 0) ? w : g_csrc[beg + j];
        float4 x0 = *(const float4*)(xl + (size_t)s0 * 128 + c0);
        float p0 = logit(x0);
        #pragma unroll
        for (int o = 1; o < 32; o <<= 1)
            if (o < grp) p0 += __shfl_xor_sync(0xffffffffu, p0, o);
        float mn = fmaxf(m, p0);
        float sc = __expf(m - mn);
        float w0 = __expf(p0 - mn);
        s = fmaf(s, sc, w0);
        acc.x = fmaf(acc.x, sc, w0 * x0.x);
        acc.y = fmaf(acc.y, sc, w0 * x0.y);
        acc.z = fmaf(acc.z, sc, w0 * x0.z);
        acc.w = fmaf(acc.w, sc, w0 * x0.w);
        m = mn;
    }
    float inv = 1.f / s;
    float4 o4 = make_float4(acc.x * inv, acc.y * inv, acc.z * inv, acc.w * inv);
    *(float4*)(out + (size_t)w * 128 + c0) = o4;
}

// ---------------- prediction heads ----------------
__global__ void __launch_bounds__(256) k_head2(const float* __restrict__ T,
                                               const float* __restrict__ w2a,
                                               const float* __restrict__ b2a,
                                               const float* __restrict__ w2b,
                                               const float* __restrict__ b2b,
                                               float* __restrict__ out, int n) {
    int w = (blockIdx.x * 256 + threadIdx.x) >> 5;
    int lane = threadIdx.x & 31;
    if (w >= n) return;
    const float* t = T + (size_t)w * 128;
    float tA = fmaf(t[lane],      w2a[lane],      t[32 + lane] * w2a[32 + lane]);
    float tB = fmaf(t[64 + lane], w2b[lane],      t[96 + lane] * w2b[32 + lane]);
    #pragma unroll
    for (int o = 16; o; o >>= 1) {
        tA += __shfl_xor_sync(0xffffffffu, tA, o);
        tB += __shfl_xor_sync(0xffffffffu, tB, o);
    }
    if (lane == 0) {
        out[(size_t)2 * w]     = tA + b2a[0];
        out[(size_t)2 * w + 1] = tB + b2b[0];
    }
}

// ---------------- launch ----------------
extern "C" void kernel_launch(void* const* d_in, const int* in_sizes, int n_in,
                              void* d_out, int out_size) {
    const float* x       = (const float*)d_in[0];
    const int*   ei      = (const int*)  d_in[1];
    const float* ln_in_g = (const float*)d_in[2];
    const float* ln_in_b = (const float*)d_in[3];
    const float* w_l1    = (const float*)d_in[4];
    const float* w_r1    = (const float*)d_in[5];
    const float* att1    = (const float*)d_in[6];
    const float* ln1_g   = (const float*)d_in[7];
    const float* ln1_b   = (const float*)d_in[8];
    const float* w_l2    = (const float*)d_in[9];
    const float* w_r2    = (const float*)d_in[10];
    const float* att2    = (const float*)d_in[11];
    const float* ln2_g   = (const float*)d_in[12];
    const float* ln2_b   = (const float*)d_in[13];
    const float* w_l3    = (const float*)d_in[14];
    const float* w_r3    = (const float*)d_in[15];
    const float* att3    = (const float*)d_in[16];
    const float* ln3_g   = (const float*)d_in[17];
    const float* ln3_b   = (const float*)d_in[18];
    const float* rtt_w1  = (const float*)d_in[19];
    const float* rtt_b1  = (const float*)d_in[20];
    const float* rtt_w2  = (const float*)d_in[21];
    const float* rtt_b2  = (const float*)d_in[22];
    const float* ret_w1  = (const float*)d_in[23];
    const float* ret_b1  = (const float*)d_in[24];
    const float* ret_w2  = (const float*)d_in[25];
    const float* ret_b2  = (const float*)d_in[26];

    const int n = in_sizes[0] / 64;
    const int e = in_sizes[1] / 2;
    const int* srcv = ei;
    const int* dstv = ei + e;

    float *p_h, *p_xl, *p_xr, *p_gg, *p_b1;
    __half *p_pk, *p_W0, *p_W1, *p_W2, *p_WH;
    cudaGetSymbolAddress((void**)&p_h,  g_h);
    cudaGetSymbolAddress((void**)&p_xl, g_xl);
    cudaGetSymbolAddress((void**)&p_xr, g_xr);
    cudaGetSymbolAddress((void**)&p_gg, g_gg);
    cudaGetSymbolAddress((void**)&p_b1, g_b1cat);
    cudaGetSymbolAddress((void**)&p_pk, g_pk);
    cudaGetSymbolAddress((void**)&p_W0, g_W0);
    cudaGetSymbolAddress((void**)&p_W1, g_W1);
    cudaGetSymbolAddress((void**)&p_W2, g_W2);
    cudaGetSymbolAddress((void**)&p_WH, g_WH);

    const int NBn = (n + 255) / 256;
    const int EB  = (e + 255) / 256;
    const int WB  = (n + 7) / 8;
    const int GBx = (n + 127) / 128;
    dim3 GB256(GBx, 2);   // NT=256 -> 2 column blocks of 128
    dim3 GB128(GBx, 1);   // NT=128 -> 1 column block

    const int SMEM = 2 * (2 * 128 * APAD * 2 + 64 * BPAD * 2);   // 108544
    cudaFuncSetAttribute((const void*)k_gemm_mma<64, 256, false>,
                         cudaFuncAttributeMaxDynamicSharedMemorySize, SMEM);
    cudaFuncSetAttribute((const void*)k_gemm_mma<128, 256, false>,
                         cudaFuncAttributeMaxDynamicSharedMemorySize, SMEM);
    cudaFuncSetAttribute((const void*)k_gemm_mma<128, 128, true>,
                         cudaFuncAttributeMaxDynamicSharedMemorySize, SMEM);

    cudaStream_t s2;
    cudaEvent_t evFork, evCSR, evW2;
    cudaStreamCreateWithFlags(&s2, cudaStreamNonBlocking);
    cudaEventCreateWithFlags(&evFork, cudaEventDisableTiming);
    cudaEventCreateWithFlags(&evCSR, cudaEventDisableTiming);
    cudaEventCreateWithFlags(&evW2, cudaEventDisableTiming);

    // --- main branch: minimal prologue before gemm0 ---
    k_ln64<<<WB, 256>>>(x, ln_in_g, ln_in_b, p_pk, n);
    k_convW<64, 256> <<<(64 * 256 + 255) / 256, 256>>>(w_l1, w_r1, p_W0);
    k_convW<128, 256><<<(128 * 256 + 255) / 256, 256>>>(w_l2, w_r2, p_W1);
    k_gemm_mma<64, 256, false><<<GB256, 256, SMEM>>>(p_pk, p_W0, p_xl, p_xr, nullptr, n);

    // --- side branch: CSR build + late weight conversions ---
    cudaEventRecord(evFork, 0);
    cudaStreamWaitEvent(s2, evFork, 0);
    k_zero   <<<NBn, 256, 0, s2>>>(n);
    k_count  <<<EB,  256, 0, s2>>>(dstv, e);
    k_scan_a <<<NBn, 256, 0, s2>>>(n);
    k_scan_b <<<1, NB_MAX, 0, s2>>>(NBn);
    k_scan_c <<<NBn, 256, 0, s2>>>(n, e);
    k_scatter<<<EB,  256, 0, s2>>>(srcv, dstv, e);
    k_sortcsr<<<NBn, 256, 0, s2>>>(n);
    cudaEventRecord(evCSR, s2);
    k_convW<128, 256><<<(128 * 256 + 255) / 256, 256, 0, s2>>>(w_l3, w_r3, p_W2);
    k_convW<128, 128><<<(128 * 128 + 255) / 256, 256, 0, s2>>>(rtt_w1, ret_w1, p_WH);
    k_biascat<<<1, 128, 0, s2>>>(rtt_b1, ret_b1);
    cudaEventRecord(evW2, s2);

    // --- layer 0 aggregation (needs CSR) ---
    cudaStreamWaitEvent(0, evCSR, 0);
    k_agg<<<WB, 256>>>(p_xl, p_xr, att1, p_gg, n, 8);
    k_ln128<<<WB, 256>>>(p_gg, ln1_g, ln1_b, nullptr, 0.f, 1, p_h, p_pk, n);

    // --- layer 1 ---
    k_gemm_mma<128, 256, false><<<GB256, 256, SMEM>>>(p_pk, p_W1, p_xl, p_xr, nullptr, n);
    k_agg<<<WB, 256>>>(p_xl, p_xr, att2, p_gg, n, 8);
    k_ln128<<<WB, 256>>>(p_gg, ln2_g, ln2_b, p_h, 0.1f, 1, p_h, p_pk, n);

    // --- layer 2 (needs W2 from side stream) ---
    cudaStreamWaitEvent(0, evW2, 0);
    k_gemm_mma<128, 256, false><<<GB256, 256, SMEM>>>(p_pk, p_W2, p_xl, p_xr, nullptr, n);
    k_agg<<<WB, 256>>>(p_xl, p_xr, att3, p_gg, n, 32);
    k_ln128<<<WB, 256>>>(p_gg, ln3_g, ln3_b, p_h, 0.1f, 0, nullptr, p_pk, n);

    // --- heads ---
    k_gemm_mma<128, 128, true><<<GB128, 256, SMEM>>>(p_pk, p_WH, p_xl, nullptr, p_b1, n);
    k_head2<<<WB, 256>>>(p_xl, rtt_w2, rtt_b2, ret_w2, ret_b2, (float*)d_out, n);
}

// round 13
// speedup vs baseline: 1.0011x; 1.0011x over previous
#include <cuda_runtime.h>
#include <cuda_fp16.h>
#include <cstdint>
#include <math.h>

#define NN 100000
#define EE 800000
#define NB_MAX 512

// ---------------- scratch (device globals; no cudaMalloc allowed) ----------------
__device__ int   g_cnt[NN];
__device__ int   g_row[NN + 1];
__device__ int   g_cur[NN];
__device__ int   g_bsum[NB_MAX];
__device__ int   g_csrc[EE];
__device__ float g_h [NN * 128];
__device__ float g_xl[NN * 128];
__device__ float g_xr[NN * 128];
__device__ float g_gg[NN * 128];
__device__ float g_b1cat[128];
__device__ __half g_pk[NN * 256];       // activation pack: [hi(K) | lo(K)] fp16 per row
__device__ __half g_W0[64 * 256];       // layer0 weight image [K x 256] fp16
__device__ __half g_W1[128 * 256];      // layer1
__device__ __half g_W2[128 * 256];      // layer2
__device__ __half g_WH[128 * 128];      // head

// ---------------- mma helpers ----------------
__device__ __forceinline__ void ldsm4(uint32_t addr, uint32_t& r0, uint32_t& r1,
                                      uint32_t& r2, uint32_t& r3) {
    asm volatile("ldmatrix.sync.aligned.m8n8.x4.shared.b16 {%0,%1,%2,%3}, [%4];"
                 : "=r"(r0), "=r"(r1), "=r"(r2), "=r"(r3) : "r"(addr));
}
__device__ __forceinline__ void ldsm4t(uint32_t addr, uint32_t& r0, uint32_t& r1,
                                       uint32_t& r2, uint32_t& r3) {
    asm volatile("ldmatrix.sync.aligned.m8n8.x4.trans.shared.b16 {%0,%1,%2,%3}, [%4];"
                 : "=r"(r0), "=r"(r1), "=r"(r2), "=r"(r3) : "r"(addr));
}
__device__ __forceinline__ void mma_f16(float* c, const uint32_t* a, uint32_t b0, uint32_t b1) {
    asm volatile(
        "mma.sync.aligned.m16n8k16.row.col.f32.f16.f16.f32 "
        "{%0,%1,%2,%3},{%4,%5,%6,%7},{%8,%9},{%0,%1,%2,%3};"
        : "+f"(c[0]), "+f"(c[1]), "+f"(c[2]), "+f"(c[3])
        : "r"(a[0]), "r"(a[1]), "r"(a[2]), "r"(a[3]), "r"(b0), "r"(b1));
}
__device__ __forceinline__ void split4h(float4 v, uint2& hi, uint2& lo) {
    __half h0 = __float2half(v.x), h1 = __float2half(v.y);
    __half h2 = __float2half(v.z), h3 = __float2half(v.w);
    __half l0 = __float2half(v.x - __half2float(h0));
    __half l1 = __float2half(v.y - __half2float(h1));
    __half l2 = __float2half(v.z - __half2float(h2));
    __half l3 = __float2half(v.w - __half2float(h3));
    hi.x = ((uint32_t)__half_as_ushort(h1) << 16) | __half_as_ushort(h0);
    hi.y = ((uint32_t)__half_as_ushort(h3) << 16) | __half_as_ushort(h2);
    lo.x = ((uint32_t)__half_as_ushort(l1) << 16) | __half_as_ushort(l0);
    lo.y = ((uint32_t)__half_as_ushort(l3) << 16) | __half_as_ushort(l2);
}

// ---------------- weight pre-convert: fp32 [K x H] pair -> fp16 image [K x NT] ----------------
template <int K, int NT>
__global__ void k_convW(const float* __restrict__ Wl, const float* __restrict__ Wr,
                        __half* __restrict__ img) {
    int idx = blockIdx.x * blockDim.x + threadIdx.x;
    if (idx >= K * NT) return;
    int k = idx / NT, col = idx % NT;
    const int H = NT / 2;
    float v = (col < H) ? Wl[k * H + col] : Wr[k * H + col - H];
    img[idx] = __float2half(v);
}

__global__ void k_biascat(const float* __restrict__ b1a, const float* __restrict__ b1b) {
    int i = threadIdx.x;
    if (i < 64) { g_b1cat[i] = b1a[i]; g_b1cat[64 + i] = b1b[i]; }
}

// ---------------- HMMA GEMM: 128 rows x 64 cols, fp16 2-term, 2-stage, 3 CTAs/SM ----------------
#define APAD 72
#define BPAD 72
template <int K, int NT, bool BIAS_RELU>
__global__ void __launch_bounds__(256, 3) k_gemm_mma(
    const __half* __restrict__ Apack,
    const __half* __restrict__ Wimg,
    float* __restrict__ out1, float* __restrict__ out2,
    const float* __restrict__ bias, int n)
{
    constexpr int C = 2 * K / 64;                 // k-chunks (64 wide): [hi chunks | lo chunks]
    constexpr int ABYTES = 128 * APAD * 2;        // 18432
    constexpr int BBYTES = 64 * BPAD * 2;         // 9216
    constexpr int STG = ABYTES + BBYTES;          // 27648 per stage
    constexpr int K2 = 2 * K;
    extern __shared__ char sm[];
    const uint32_t sbase = (uint32_t)__cvta_generic_to_shared(sm);
    const int tid = threadIdx.x, lane = tid & 31, wid = tid >> 5;
    const int wm = wid & 3, wn = wid >> 2;        // 4 warps M (32 rows), 2 warps N (32 cols)
    const int row0 = blockIdx.x * 128;
    const int col0 = blockIdx.y * 64;             // column block within NT

    auto loadChunk = [&](int c) {
        const int per = K / 64;
        const int t = c / per;                    // 0 = hi half, 1 = lo half
        const int within = c - t * per;
        const int a_off = t * K + within * 64;
        const int brow = within * 64;             // same W for both halves
        const uint32_t sA = sbase + (uint32_t)(c & 1) * STG;
        const uint32_t sB = sA + ABYTES;
        #pragma unroll
        for (int i = tid; i < 1024; i += 256) {                 // A: 128 x 64
            int r = i >> 3, cc = (i & 7) * 8;
            int grow = row0 + r; if (grow > n - 1) grow = n - 1;
            uint32_t dst = sA + (uint32_t)(r * APAD + cc) * 2;
            const __half* src = Apack + (size_t)grow * K2 + a_off + cc;
            asm volatile("cp.async.ca.shared.global [%0], [%1], 16;" :: "r"(dst), "l"(src));
        }
        #pragma unroll
        for (int i = tid; i < 512; i += 256) {                  // B: 64 x 64
            int r = i >> 3, cc = (i & 7) * 8;
            uint32_t dst = sB + (uint32_t)(r * BPAD + cc) * 2;
            const __half* src = Wimg + (size_t)(brow + r) * NT + col0 + cc;
            asm volatile("cp.async.ca.shared.global [%0], [%1], 16;" :: "r"(dst), "l"(src));
        }
        asm volatile("cp.async.commit_group;" ::: "memory");
    };

    float acc[2][4][4];
    #pragma unroll
    for (int i = 0; i < 2; i++)
        #pragma unroll
        for (int j = 0; j < 4; j++)
            #pragma unroll
            for (int q = 0; q < 4; q++) acc[i][j][q] = 0.f;

    loadChunk(0);

    for (int c = 0; c < C; c++) {
        if (c + 1 < C) {
            loadChunk(c + 1);
            asm volatile("cp.async.wait_group 1;" ::: "memory");
        } else {
            asm volatile("cp.async.wait_group 0;" ::: "memory");
        }
        __syncthreads();
        const uint32_t sA = sbase + (uint32_t)(c & 1) * STG;
        const uint32_t sB = sA + ABYTES;
        #pragma unroll
        for (int ks = 0; ks < 4; ks++) {
            uint32_t a[2][4];
            #pragma unroll
            for (int mi = 0; mi < 2; mi++) {
                uint32_t addr = sA +
                    (uint32_t)((wm * 32 + mi * 16 + (lane & 15)) * APAD + ks * 16 + 8 * (lane >> 4)) * 2;
                ldsm4(addr, a[mi][0], a[mi][1], a[mi][2], a[mi][3]);
            }
            #pragma unroll
            for (int ng = 0; ng < 2; ng++) {
                uint32_t b0, b1, b2, b3;
                uint32_t addr = sB +
                    (uint32_t)((ks * 16 + (lane & 15)) * BPAD + wn * 32 + ng * 16 + 8 * (lane >> 4)) * 2;
                ldsm4t(addr, b0, b1, b2, b3);
                mma_f16(acc[0][ng * 2],     a[0], b0, b1);
                mma_f16(acc[0][ng * 2 + 1], a[0], b2, b3);
                mma_f16(acc[1][ng * 2],     a[1], b0, b1);
                mma_f16(acc[1][ng * 2 + 1], a[1], b2, b3);
            }
        }
        if (c + 1 < C) __syncthreads();   // all warps done reading buf (c&1) before it is reloaded
    }

    // epilogue
    const int rb = row0 + wm * 32 + (lane >> 2);
    const int cbl = wn * 32 + (lane & 3) * 2;     // col within 64-wide block
    #pragma unroll
    for (int mi = 0; mi < 2; mi++) {
        #pragma unroll
        for (int ni = 0; ni < 4; ni++) {
            int col = col0 + cbl + ni * 8;        // global col within NT
            #pragma unroll
            for (int h = 0; h < 2; h++) {
                int rg = rb + mi * 16 + h * 8;
                if (rg < n) {
                    float2 v;
                    v.x = acc[mi][ni][h * 2 + 0];
                    v.y = acc[mi][ni][h * 2 + 1];
                    if (BIAS_RELU) {
                        v.x = fmaxf(v.x + bias[col], 0.f);
                        v.y = fmaxf(v.y + bias[col + 1], 0.f);
                    }
                    float* dst = out1;
                    int cc = col;
                    if (NT == 256 && col >= 128) { dst = out2; cc = col - 128; }
                    *(float2*)(dst + (size_t)rg * 128 + cc) = v;
                }
            }
        }
    }
}

// ---------------- CSR build ----------------
__global__ void k_zero(int n) {
    int i = blockIdx.x * blockDim.x + threadIdx.x;
    if (i < n) g_cnt[i] = 0;
}

__global__ void k_count(const int* __restrict__ dstv, int e) {
    int i = blockIdx.x * blockDim.x + threadIdx.x;
    if (i < e) atomicAdd(&g_cnt[dstv[i]], 1);
}

__global__ void k_scan_a(int n) {
    __shared__ int sh[256];
    int i = blockIdx.x * 256 + threadIdx.x;
    int v = (i < n) ? g_cnt[i] : 0;
    sh[threadIdx.x] = v;
    __syncthreads();
    #pragma unroll
    for (int o = 1; o < 256; o <<= 1) {
        int t = (threadIdx.x >= o) ? sh[threadIdx.x - o] : 0;
        __syncthreads();
        sh[threadIdx.x] += t;
        __syncthreads();
    }
    if (i < n) g_row[i] = sh[threadIdx.x] - v;
    if (threadIdx.x == 255) g_bsum[blockIdx.x] = sh[255];
}

__global__ void k_scan_b(int nb) {
    __shared__ int sh[NB_MAX];
    int t = threadIdx.x;
    int v = (t < nb) ? g_bsum[t] : 0;
    sh[t] = v;
    __syncthreads();
    #pragma unroll
    for (int o = 1; o < NB_MAX; o <<= 1) {
        int u = (t >= o) ? sh[t - o] : 0;
        __syncthreads();
        sh[t] += u;
        __syncthreads();
    }
    if (t < nb) g_bsum[t] = sh[t] - v;
}

__global__ void k_scan_c(int n, int e) {
    int i = blockIdx.x * 256 + threadIdx.x;
    if (i < n) {
        int r = g_row[i] + g_bsum[blockIdx.x];
        g_row[i] = r;
        g_cur[i] = r;
    }
    if (i == 0) g_row[n] = e;
}

__global__ void k_scatter(const int* __restrict__ srcv, const int* __restrict__ dstv, int e) {
    int i = blockIdx.x * blockDim.x + threadIdx.x;
    if (i < e) {
        int pos = atomicAdd(&g_cur[dstv[i]], 1);
        g_csrc[pos] = srcv[i];
    }
}

__global__ void k_sortcsr(int n) {
    int i = blockIdx.x * blockDim.x + threadIdx.x;
    if (i >= n) return;
    int b = g_row[i], e2 = g_row[i + 1];
    for (int a = b + 1; a < e2; a++) {
        int v = g_csrc[a];
        int k = a;
        while (k > b && g_csrc[k - 1] > v) { g_csrc[k] = g_csrc[k - 1]; k--; }
        g_csrc[k] = v;
    }
}

// ---------------- LayerNorm kernels (write fp16 hi/lo pack for the GEMM) ----------------
__global__ void __launch_bounds__(256) k_ln64(const float* __restrict__ x,
                                              const float* __restrict__ g,
                                              const float* __restrict__ b,
                                              __half* __restrict__ pack, int n) {
    int w = (blockIdx.x * 256 + threadIdx.x) >> 5;
    int lane = threadIdx.x & 31;
    if (w >= n) return;
    float2 v = *(const float2*)(x + (size_t)w * 64 + lane * 2);
    float s = v.x + v.y;
    float q = v.x * v.x + v.y * v.y;
    #pragma unroll
    for (int o = 16; o; o >>= 1) {
        s += __shfl_xor_sync(0xffffffffu, s, o);
        q += __shfl_xor_sync(0xffffffffu, q, o);
    }
    float m  = s * (1.f / 64.f);
    float var = q * (1.f / 64.f) - m * m;
    float rs = rsqrtf(var + 1e-5f);
    float2 gg = *(const float2*)(g + lane * 2);
    float2 bb = *(const float2*)(b + lane * 2);
    float y0 = (v.x - m) * rs * gg.x + bb.x;
    float y1 = (v.y - m) * rs * gg.y + bb.y;
    __half h0 = __float2half(y0), h1 = __float2half(y1);
    __half l0 = __float2half(y0 - __half2float(h0));
    __half l1 = __float2half(y1 - __half2float(h1));
    uint32_t hw = ((uint32_t)__half_as_ushort(h1) << 16) | __half_as_ushort(h0);
    uint32_t lw = ((uint32_t)__half_as_ushort(l1) << 16) | __half_as_ushort(l0);
    *(uint32_t*)(pack + (size_t)w * 128 + lane * 2)      = hw;
    *(uint32_t*)(pack + (size_t)w * 128 + 64 + lane * 2) = lw;
}

__global__ void __launch_bounds__(256) k_ln128(const float* __restrict__ in,
                                               const float* __restrict__ g,
                                               const float* __restrict__ b,
                                               const float* __restrict__ res,
                                               float rscale, int doRelu,
                                               float* __restrict__ outf,
                                               __half* __restrict__ pack, int n) {
    int w = (blockIdx.x * 256 + threadIdx.x) >> 5;
    int lane = threadIdx.x & 31;
    if (w >= n) return;
    int c0 = lane * 4;
    float4 v = *(const float4*)(in + (size_t)w * 128 + c0);
    float s = v.x + v.y + v.z + v.w;
    float q = v.x * v.x + v.y * v.y + v.z * v.z + v.w * v.w;
    #pragma unroll
    for (int o = 16; o; o >>= 1) {
        s += __shfl_xor_sync(0xffffffffu, s, o);
        q += __shfl_xor_sync(0xffffffffu, q, o);
    }
    float m   = s * (1.f / 128.f);
    float var = q * (1.f / 128.f) - m * m;
    float rs  = rsqrtf(var + 1e-5f);
    float4 gg = *(const float4*)(g + c0);
    float4 bb = *(const float4*)(b + c0);
    float4 y;
    y.x = (v.x - m) * rs * gg.x + bb.x;
    y.y = (v.y - m) * rs * gg.y + bb.y;
    y.z = (v.z - m) * rs * gg.z + bb.z;
    y.w = (v.w - m) * rs * gg.w + bb.w;
    if (res) {
        float4 r4 = *(const float4*)(res + (size_t)w * 128 + c0);
        y.x += rscale * r4.x; y.y += rscale * r4.y;
        y.z += rscale * r4.z; y.w += rscale * r4.w;
    }
    if (doRelu) {
        y.x = fmaxf(y.x, 0.f); y.y = fmaxf(y.y, 0.f);
        y.z = fmaxf(y.z, 0.f); y.w = fmaxf(y.w, 0.f);
    }
    if (outf) *(float4*)(outf + (size_t)w * 128 + c0) = y;
    uint2 hi, lo;
    split4h(y, hi, lo);
    *(uint2*)(pack + (size_t)w * 256 + c0)       = hi;
    *(uint2*)(pack + (size_t)w * 256 + 128 + c0) = lo;
}

// ---------------- GATv2 aggregation: warp per dst node, online softmax, 2-edge ILP ----------------
__global__ void __launch_bounds__(256) k_agg(const float* __restrict__ xl,
                                             const float* __restrict__ xr,
                                             const float* __restrict__ att,
                                             float* __restrict__ out, int n, int grp) {
    int w = (blockIdx.x * 256 + threadIdx.x) >> 5;
    int lane = threadIdx.x & 31;
    if (w >= n) return;
    int c0 = lane * 4;
    float4 a4 = *(const float4*)(att + c0);
    float4 r4 = *(const float4*)(xr + (size_t)w * 128 + c0);
    int beg = g_row[w], deg = g_row[w + 1] - beg;
    float m = -1e30f, s = 0.f;
    float4 acc = make_float4(0.f, 0.f, 0.f, 0.f);

    auto logit = [&](float4 x) -> float {
        float e0 = x.x + r4.x, e1 = x.y + r4.y, e2 = x.z + r4.z, e3 = x.w + r4.w;
        e0 = (e0 > 0.f) ? e0 : 0.2f * e0;
        e1 = (e1 > 0.f) ? e1 : 0.2f * e1;
        e2 = (e2 > 0.f) ? e2 : 0.2f * e2;
        e3 = (e3 > 0.f) ? e3 : 0.2f * e3;
        return fmaf(a4.x, e0, fmaf(a4.y, e1, fmaf(a4.z, e2, a4.w * e3)));
    };

    int j = -1;                              // j == -1 is the self-loop
    for (; j + 1 < deg; j += 2) {
        int s0 = (j < 0) ? w : g_csrc[beg + j];
        int s1 = g_csrc[beg + j + 1];
        float4 x0 = *(const float4*)(xl + (size_t)s0 * 128 + c0);
        float4 x1 = *(const float4*)(xl + (size_t)s1 * 128 + c0);
        float p0 = logit(x0);
        float p1 = logit(x1);
        #pragma unroll
        for (int o = 1; o < 32; o <<= 1)
            if (o < grp) {
                p0 += __shfl_xor_sync(0xffffffffu, p0, o);
                p1 += __shfl_xor_sync(0xffffffffu, p1, o);
            }
        float mn = fmaxf(m, fmaxf(p0, p1));
        float sc = __expf(m - mn);
        float w0 = __expf(p0 - mn);
        float w1 = __expf(p1 - mn);
        s = fmaf(s, sc, w0 + w1);
        acc.x = fmaf(acc.x, sc, fmaf(w0, x0.x, w1 * x1.x));
        acc.y = fmaf(acc.y, sc, fmaf(w0, x0.y, w1 * x1.y));
        acc.z = fmaf(acc.z, sc, fmaf(w0, x0.z, w1 * x1.z));
        acc.w = fmaf(acc.w, sc, fmaf(w0, x0.w, w1 * x1.w));
        m = mn;
    }
    if (j < deg) {                           // leftover single edge (or lone self-loop)
        int s0 = (j < 0) ? w : g_csrc[beg + j];
        float4 x0 = *(const float4*)(xl + (size_t)s0 * 128 + c0);
        float p0 = logit(x0);
        #pragma unroll
        for (int o = 1; o < 32; o <<= 1)
            if (o < grp) p0 += __shfl_xor_sync(0xffffffffu, p0, o);
        float mn = fmaxf(m, p0);
        float sc = __expf(m - mn);
        float w0 = __expf(p0 - mn);
        s = fmaf(s, sc, w0);
        acc.x = fmaf(acc.x, sc, w0 * x0.x);
        acc.y = fmaf(acc.y, sc, w0 * x0.y);
        acc.z = fmaf(acc.z, sc, w0 * x0.z);
        acc.w = fmaf(acc.w, sc, w0 * x0.w);
        m = mn;
    }
    float inv = 1.f / s;
    float4 o4 = make_float4(acc.x * inv, acc.y * inv, acc.z * inv, acc.w * inv);
    *(float4*)(out + (size_t)w * 128 + c0) = o4;
}

// ---------------- prediction heads ----------------
__global__ void __launch_bounds__(256) k_head2(const float* __restrict__ T,
                                               const float* __restrict__ w2a,
                                               const float* __restrict__ b2a,
                                               const float* __restrict__ w2b,
                                               const float* __restrict__ b2b,
                                               float* __restrict__ out, int n) {
    int w = (blockIdx.x * 256 + threadIdx.x) >> 5;
    int lane = threadIdx.x & 31;
    if (w >= n) return;
    const float* t = T + (size_t)w * 128;
    float tA = fmaf(t[lane],      w2a[lane],      t[32 + lane] * w2a[32 + lane]);
    float tB = fmaf(t[64 + lane], w2b[lane],      t[96 + lane] * w2b[32 + lane]);
    #pragma unroll
    for (int o = 16; o; o >>= 1) {
        tA += __shfl_xor_sync(0xffffffffu, tA, o);
        tB += __shfl_xor_sync(0xffffffffu, tB, o);
    }
    if (lane == 0) {
        out[(size_t)2 * w]     = tA + b2a[0];
        out[(size_t)2 * w + 1] = tB + b2b[0];
    }
}

// ---------------- launch ----------------
extern "C" void kernel_launch(void* const* d_in, const int* in_sizes, int n_in,
                              void* d_out, int out_size) {
    const float* x       = (const float*)d_in[0];
    const int*   ei      = (const int*)  d_in[1];
    const float* ln_in_g = (const float*)d_in[2];
    const float* ln_in_b = (const float*)d_in[3];
    const float* w_l1    = (const float*)d_in[4];
    const float* w_r1    = (const float*)d_in[5];
    const float* att1    = (const float*)d_in[6];
    const float* ln1_g   = (const float*)d_in[7];
    const float* ln1_b   = (const float*)d_in[8];
    const float* w_l2    = (const float*)d_in[9];
    const float* w_r2    = (const float*)d_in[10];
    const float* att2    = (const float*)d_in[11];
    const float* ln2_g   = (const float*)d_in[12];
    const float* ln2_b   = (const float*)d_in[13];
    const float* w_l3    = (const float*)d_in[14];
    const float* w_r3    = (const float*)d_in[15];
    const float* att3    = (const float*)d_in[16];
    const float* ln3_g   = (const float*)d_in[17];
    const float* ln3_b   = (const float*)d_in[18];
    const float* rtt_w1  = (const float*)d_in[19];
    const float* rtt_b1  = (const float*)d_in[20];
    const float* rtt_w2  = (const float*)d_in[21];
    const float* rtt_b2  = (const float*)d_in[22];
    const float* ret_w1  = (const float*)d_in[23];
    const float* ret_b1  = (const float*)d_in[24];
    const float* ret_w2  = (const float*)d_in[25];
    const float* ret_b2  = (const float*)d_in[26];

    const int n = in_sizes[0] / 64;
    const int e = in_sizes[1] / 2;
    const int* srcv = ei;
    const int* dstv = ei + e;

    float *p_h, *p_xl, *p_xr, *p_gg, *p_b1;
    __half *p_pk, *p_W0, *p_W1, *p_W2, *p_WH;
    cudaGetSymbolAddress((void**)&p_h,  g_h);
    cudaGetSymbolAddress((void**)&p_xl, g_xl);
    cudaGetSymbolAddress((void**)&p_xr, g_xr);
    cudaGetSymbolAddress((void**)&p_gg, g_gg);
    cudaGetSymbolAddress((void**)&p_b1, g_b1cat);
    cudaGetSymbolAddress((void**)&p_pk, g_pk);
    cudaGetSymbolAddress((void**)&p_W0, g_W0);
    cudaGetSymbolAddress((void**)&p_W1, g_W1);
    cudaGetSymbolAddress((void**)&p_W2, g_W2);
    cudaGetSymbolAddress((void**)&p_WH, g_WH);

    const int NBn = (n + 255) / 256;
    const int EB  = (e + 255) / 256;
    const int WB  = (n + 7) / 8;
    const int GBx = (n + 127) / 128;
    dim3 GB256(GBx, 4);   // NT=256 -> 4 column blocks of 64
    dim3 GB128(GBx, 2);   // NT=128 -> 2 column blocks of 64

    const int SMEM = 2 * (128 * APAD * 2 + 64 * BPAD * 2);   // 55296 (2 stages)
    cudaFuncSetAttribute((const void*)k_gemm_mma<64, 256, false>,
                         cudaFuncAttributeMaxDynamicSharedMemorySize, SMEM);
    cudaFuncSetAttribute((const void*)k_gemm_mma<128, 256, false>,
                         cudaFuncAttributeMaxDynamicSharedMemorySize, SMEM);
    cudaFuncSetAttribute((const void*)k_gemm_mma<128, 128, true>,
                         cudaFuncAttributeMaxDynamicSharedMemorySize, SMEM);

    cudaStream_t s2;
    cudaEvent_t evFork, evCSR, evW2;
    cudaStreamCreateWithFlags(&s2, cudaStreamNonBlocking);
    cudaEventCreateWithFlags(&evFork, cudaEventDisableTiming);
    cudaEventCreateWithFlags(&evCSR, cudaEventDisableTiming);
    cudaEventCreateWithFlags(&evW2, cudaEventDisableTiming);

    // --- main branch: minimal prologue before gemm0 ---
    k_ln64<<<WB, 256>>>(x, ln_in_g, ln_in_b, p_pk, n);
    k_convW<64, 256> <<<(64 * 256 + 255) / 256, 256>>>(w_l1, w_r1, p_W0);
    k_convW<128, 256><<<(128 * 256 + 255) / 256, 256>>>(w_l2, w_r2, p_W1);
    k_gemm_mma<64, 256, false><<<GB256, 256, SMEM>>>(p_pk, p_W0, p_xl, p_xr, nullptr, n);

    // --- side branch: CSR build + late weight conversions ---
    cudaEventRecord(evFork, 0);
    cudaStreamWaitEvent(s2, evFork, 0);
    k_zero   <<<NBn, 256, 0, s2>>>(n);
    k_count  <<<EB,  256, 0, s2>>>(dstv, e);
    k_scan_a <<<NBn, 256, 0, s2>>>(n);
    k_scan_b <<<1, NB_MAX, 0, s2>>>(NBn);
    k_scan_c <<<NBn, 256, 0, s2>>>(n, e);
    k_scatter<<<EB,  256, 0, s2>>>(srcv, dstv, e);
    k_sortcsr<<<NBn, 256, 0, s2>>>(n);
    cudaEventRecord(evCSR, s2);
    k_convW<128, 256><<<(128 * 256 + 255) / 256, 256, 0, s2>>>(w_l3, w_r3, p_W2);
    k_convW<128, 128><<<(128 * 128 + 255) / 256, 256, 0, s2>>>(rtt_w1, ret_w1, p_WH);
    k_biascat<<<1, 128, 0, s2>>>(rtt_b1, ret_b1);
    cudaEventRecord(evW2, s2);

    // --- layer 0 aggregation (needs CSR) ---
    cudaStreamWaitEvent(0, evCSR, 0);
    k_agg<<<WB, 256>>>(p_xl, p_xr, att1, p_gg, n, 8);
    k_ln128<<<WB, 256>>>(p_gg, ln1_g, ln1_b, nullptr, 0.f, 1, p_h, p_pk, n);

    // --- layer 1 ---
    k_gemm_mma<128, 256, false><<<GB256, 256, SMEM>>>(p_pk, p_W1, p_xl, p_xr, nullptr, n);
    k_agg<<<WB, 256>>>(p_xl, p_xr, att2, p_gg, n, 8);
    k_ln128<<<WB, 256>>>(p_gg, ln2_g, ln2_b, p_h, 0.1f, 1, p_h, p_pk, n);

    // --- layer 2 (needs W2 from side stream) ---
    cudaStreamWaitEvent(0, evW2, 0);
    k_gemm_mma<128, 256, false><<<GB256, 256, SMEM>>>(p_pk, p_W2, p_xl, p_xr, nullptr, n);
    k_agg<<<WB, 256>>>(p_xl, p_xr, att3, p_gg, n, 32);
    k_ln128<<<WB, 256>>>(p_gg, ln3_g, ln3_b, p_h, 0.1f, 0, nullptr, p_pk, n);

    // --- heads ---
    k_gemm_mma<128, 128, true><<<GB128, 256, SMEM>>>(p_pk, p_WH, p_xl, nullptr, p_b1, n);
    k_head2<<<WB, 256>>>(p_xl, rtt_w2, rtt_b2, ret_w2, ret_b2, (float*)d_out, n);
}

// round 14
// speedup vs baseline: 1.0267x; 1.0256x over previous
#include <cuda_runtime.h>
#include <cuda_fp16.h>
#include <cstdint>
#include <math.h>

#define NN 100000
#define EE 800000
#define NB_MAX 512

// ---------------- scratch (device globals; no cudaMalloc allowed) ----------------
__device__ int   g_cnt[NN];
__device__ int   g_row[NN + 1];
__device__ int   g_cur[NN];
__device__ int   g_bsum[NB_MAX];
__device__ int   g_csrc[EE];
__device__ float g_h [NN * 128];
__device__ float g_xl[NN * 128];     // holds fp16 xl (reinterpreted) or fp32 head output
__device__ float g_xr[NN * 128];     // holds fp16 xr (reinterpreted)
__device__ float g_gg[NN * 128];
__device__ float g_b1cat[128];
__device__ __half g_pk[NN * 256];       // activation pack: [hi(K) | lo(K)] fp16 per row
__device__ __half g_W0[64 * 256];       // layer0 weight image [K x 256] fp16
__device__ __half g_W1[128 * 256];      // layer1
__device__ __half g_W2[128 * 256];      // layer2
__device__ __half g_WH[128 * 128];      // head

// ---------------- mma helpers ----------------
__device__ __forceinline__ void ldsm4(uint32_t addr, uint32_t& r0, uint32_t& r1,
                                      uint32_t& r2, uint32_t& r3) {
    asm volatile("ldmatrix.sync.aligned.m8n8.x4.shared.b16 {%0,%1,%2,%3}, [%4];"
                 : "=r"(r0), "=r"(r1), "=r"(r2), "=r"(r3) : "r"(addr));
}
__device__ __forceinline__ void ldsm4t(uint32_t addr, uint32_t& r0, uint32_t& r1,
                                       uint32_t& r2, uint32_t& r3) {
    asm volatile("ldmatrix.sync.aligned.m8n8.x4.trans.shared.b16 {%0,%1,%2,%3}, [%4];"
                 : "=r"(r0), "=r"(r1), "=r"(r2), "=r"(r3) : "r"(addr));
}
__device__ __forceinline__ void mma_f16(float* c, const uint32_t* a, uint32_t b0, uint32_t b1) {
    asm volatile(
        "mma.sync.aligned.m16n8k16.row.col.f32.f16.f16.f32 "
        "{%0,%1,%2,%3},{%4,%5,%6,%7},{%8,%9},{%0,%1,%2,%3};"
        : "+f"(c[0]), "+f"(c[1]), "+f"(c[2]), "+f"(c[3])
        : "r"(a[0]), "r"(a[1]), "r"(a[2]), "r"(a[3]), "r"(b0), "r"(b1));
}
__device__ __forceinline__ void split4h(float4 v, uint2& hi, uint2& lo) {
    __half h0 = __float2half(v.x), h1 = __float2half(v.y);
    __half h2 = __float2half(v.z), h3 = __float2half(v.w);
    __half l0 = __float2half(v.x - __half2float(h0));
    __half l1 = __float2half(v.y - __half2float(h1));
    __half l2 = __float2half(v.z - __half2float(h2));
    __half l3 = __float2half(v.w - __half2float(h3));
    hi.x = ((uint32_t)__half_as_ushort(h1) << 16) | __half_as_ushort(h0);
    hi.y = ((uint32_t)__half_as_ushort(h3) << 16) | __half_as_ushort(h2);
    lo.x = ((uint32_t)__half_as_ushort(l1) << 16) | __half_as_ushort(l0);
    lo.y = ((uint32_t)__half_as_ushort(l3) << 16) | __half_as_ushort(l2);
}

// ---------------- weight pre-convert: fp32 [K x H] pair -> fp16 image [K x NT] ----------------
template <int K, int NT>
__global__ void k_convW(const float* __restrict__ Wl, const float* __restrict__ Wr,
                        __half* __restrict__ img) {
    int idx = blockIdx.x * blockDim.x + threadIdx.x;
    if (idx >= K * NT) return;
    int k = idx / NT, col = idx % NT;
    const int H = NT / 2;
    float v = (col < H) ? Wl[k * H + col] : Wr[k * H + col - H];
    img[idx] = __float2half(v);
}

__global__ void k_biascat(const float* __restrict__ b1a, const float* __restrict__ b1b) {
    int i = threadIdx.x;
    if (i < 64) { g_b1cat[i] = b1a[i]; g_b1cat[64 + i] = b1b[i]; }
}

// ---------------- HMMA GEMM: 128 rows x 64 cols, fp16 2-term, 3-stage, 2 CTAs/SM ----------------
#define APAD 72
#define BPAD 72
template <int K, int NT, bool BIAS_RELU, bool HALF_OUT>
__global__ void __launch_bounds__(256, 2) k_gemm_mma(
    const __half* __restrict__ Apack,
    const __half* __restrict__ Wimg,
    float* __restrict__ out1, float* __restrict__ out2,
    const float* __restrict__ bias, int n)
{
    constexpr int C = 2 * K / 64;                 // k-chunks (64 wide): [hi chunks | lo chunks]
    constexpr int ABYTES = 128 * APAD * 2;        // 18432
    constexpr int BBYTES = 64 * BPAD * 2;         // 9216
    constexpr int STG = ABYTES + BBYTES;          // 27648 per stage
    constexpr int K2 = 2 * K;
    extern __shared__ char sm[];
    const uint32_t sbase = (uint32_t)__cvta_generic_to_shared(sm);
    const int tid = threadIdx.x, lane = tid & 31, wid = tid >> 5;
    const int wm = wid & 3, wn = wid >> 2;        // 4 warps M (32 rows), 2 warps N (32 cols)
    const int row0 = blockIdx.x * 128;
    const int col0 = blockIdx.y * 64;             // column block within NT

    auto loadChunk = [&](int c) {
        const int per = K / 64;
        const int t = c / per;                    // 0 = hi half, 1 = lo half
        const int within = c - t * per;
        const int a_off = t * K + within * 64;
        const int brow = within * 64;             // same W for both halves
        const uint32_t sA = sbase + (uint32_t)(c % 3) * STG;
        const uint32_t sB = sA + ABYTES;
        #pragma unroll
        for (int i = tid; i < 1024; i += 256) {                 // A: 128 x 64
            int r = i >> 3, cc = (i & 7) * 8;
            int grow = row0 + r; if (grow > n - 1) grow = n - 1;
            uint32_t dst = sA + (uint32_t)(r * APAD + cc) * 2;
            const __half* src = Apack + (size_t)grow * K2 + a_off + cc;
            asm volatile("cp.async.ca.shared.global [%0], [%1], 16;" :: "r"(dst), "l"(src));
        }
        #pragma unroll
        for (int i = tid; i < 512; i += 256) {                  // B: 64 x 64
            int r = i >> 3, cc = (i & 7) * 8;
            uint32_t dst = sB + (uint32_t)(r * BPAD + cc) * 2;
            const __half* src = Wimg + (size_t)(brow + r) * NT + col0 + cc;
            asm volatile("cp.async.ca.shared.global [%0], [%1], 16;" :: "r"(dst), "l"(src));
        }
        asm volatile("cp.async.commit_group;" ::: "memory");
    };

    float acc[2][4][4];
    #pragma unroll
    for (int i = 0; i < 2; i++)
        #pragma unroll
        for (int j = 0; j < 4; j++)
            #pragma unroll
            for (int q = 0; q < 4; q++) acc[i][j][q] = 0.f;

    loadChunk(0);
    loadChunk(1);

    for (int c = 0; c < C; c++) {
        if (c < C - 1) asm volatile("cp.async.wait_group 1;" ::: "memory");
        else           asm volatile("cp.async.wait_group 0;" ::: "memory");
        __syncthreads();
        if (c + 2 < C) loadChunk(c + 2);
        const uint32_t sA = sbase + (uint32_t)(c % 3) * STG;
        const uint32_t sB = sA + ABYTES;
        #pragma unroll
        for (int ks = 0; ks < 4; ks++) {
            uint32_t a[2][4];
            #pragma unroll
            for (int mi = 0; mi < 2; mi++) {
                uint32_t addr = sA +
                    (uint32_t)((wm * 32 + mi * 16 + (lane & 15)) * APAD + ks * 16 + 8 * (lane >> 4)) * 2;
                ldsm4(addr, a[mi][0], a[mi][1], a[mi][2], a[mi][3]);
            }
            #pragma unroll
            for (int ng = 0; ng < 2; ng++) {
                uint32_t b0, b1, b2, b3;
                uint32_t addr = sB +
                    (uint32_t)((ks * 16 + (lane & 15)) * BPAD + wn * 32 + ng * 16 + 8 * (lane >> 4)) * 2;
                ldsm4t(addr, b0, b1, b2, b3);
                mma_f16(acc[0][ng * 2],     a[0], b0, b1);
                mma_f16(acc[0][ng * 2 + 1], a[0], b2, b3);
                mma_f16(acc[1][ng * 2],     a[1], b0, b1);
                mma_f16(acc[1][ng * 2 + 1], a[1], b2, b3);
            }
        }
    }

    // epilogue
    const int rb = row0 + wm * 32 + (lane >> 2);
    const int cbl = wn * 32 + (lane & 3) * 2;     // col within 64-wide block
    #pragma unroll
    for (int mi = 0; mi < 2; mi++) {
        #pragma unroll
        for (int ni = 0; ni < 4; ni++) {
            int col = col0 + cbl + ni * 8;        // global col within NT
            #pragma unroll
            for (int h = 0; h < 2; h++) {
                int rg = rb + mi * 16 + h * 8;
                if (rg < n) {
                    float2 v;
                    v.x = acc[mi][ni][h * 2 + 0];
                    v.y = acc[mi][ni][h * 2 + 1];
                    if (BIAS_RELU) {
                        v.x = fmaxf(v.x + bias[col], 0.f);
                        v.y = fmaxf(v.y + bias[col + 1], 0.f);
                    }
                    float* dst = out1;
                    int cc = col;
                    if (NT == 256 && col >= 128) { dst = out2; cc = col - 128; }
                    if (HALF_OUT) {
                        __half2 hv = __floats2half2_rn(v.x, v.y);
                        *(__half2*)((__half*)dst + (size_t)rg * 128 + cc) = hv;
                    } else {
                        *(float2*)(dst + (size_t)rg * 128 + cc) = v;
                    }
                }
            }
        }
    }
}

// ---------------- CSR build ----------------
__global__ void k_zero(int n) {
    int i = blockIdx.x * blockDim.x + threadIdx.x;
    if (i < n) g_cnt[i] = 0;
}

__global__ void k_count(const int* __restrict__ dstv, int e) {
    int i = blockIdx.x * blockDim.x + threadIdx.x;
    if (i < e) atomicAdd(&g_cnt[dstv[i]], 1);
}

__global__ void k_scan_a(int n) {
    __shared__ int sh[256];
    int i = blockIdx.x * 256 + threadIdx.x;
    int v = (i < n) ? g_cnt[i] : 0;
    sh[threadIdx.x] = v;
    __syncthreads();
    #pragma unroll
    for (int o = 1; o < 256; o <<= 1) {
        int t = (threadIdx.x >= o) ? sh[threadIdx.x - o] : 0;
        __syncthreads();
        sh[threadIdx.x] += t;
        __syncthreads();
    }
    if (i < n) g_row[i] = sh[threadIdx.x] - v;
    if (threadIdx.x == 255) g_bsum[blockIdx.x] = sh[255];
}

__global__ void k_scan_b(int nb) {
    __shared__ int sh[NB_MAX];
    int t = threadIdx.x;
    int v = (t < nb) ? g_bsum[t] : 0;
    sh[t] = v;
    __syncthreads();
    #pragma unroll
    for (int o = 1; o < NB_MAX; o <<= 1) {
        int u = (t >= o) ? sh[t - o] : 0;
        __syncthreads();
        sh[t] += u;
        __syncthreads();
    }
    if (t < nb) g_bsum[t] = sh[t] - v;
}

__global__ void k_scan_c(int n, int e) {
    int i = blockIdx.x * 256 + threadIdx.x;
    if (i < n) {
        int r = g_row[i] + g_bsum[blockIdx.x];
        g_row[i] = r;
        g_cur[i] = r;
    }
    if (i == 0) g_row[n] = e;
}

__global__ void k_scatter(const int* __restrict__ srcv, const int* __restrict__ dstv, int e) {
    int i = blockIdx.x * blockDim.x + threadIdx.x;
    if (i < e) {
        int pos = atomicAdd(&g_cur[dstv[i]], 1);
        g_csrc[pos] = srcv[i];
    }
}

__global__ void k_sortcsr(int n) {
    int i = blockIdx.x * blockDim.x + threadIdx.x;
    if (i >= n) return;
    int b = g_row[i], e2 = g_row[i + 1];
    for (int a = b + 1; a < e2; a++) {
        int v = g_csrc[a];
        int k = a;
        while (k > b && g_csrc[k - 1] > v) { g_csrc[k] = g_csrc[k - 1]; k--; }
        g_csrc[k] = v;
    }
}

// ---------------- LayerNorm kernels (write fp16 hi/lo pack for the GEMM) ----------------
__global__ void __launch_bounds__(256) k_ln64(const float* __restrict__ x,
                                              const float* __restrict__ g,
                                              const float* __restrict__ b,
                                              __half* __restrict__ pack, int n) {
    int w = (blockIdx.x * 256 + threadIdx.x) >> 5;
    int lane = threadIdx.x & 31;
    if (w >= n) return;
    float2 v = *(const float2*)(x + (size_t)w * 64 + lane * 2);
    float s = v.x + v.y;
    float q = v.x * v.x + v.y * v.y;
    #pragma unroll
    for (int o = 16; o; o >>= 1) {
        s += __shfl_xor_sync(0xffffffffu, s, o);
        q += __shfl_xor_sync(0xffffffffu, q, o);
    }
    float m  = s * (1.f / 64.f);
    float var = q * (1.f / 64.f) - m * m;
    float rs = rsqrtf(var + 1e-5f);
    float2 gg = *(const float2*)(g + lane * 2);
    float2 bb = *(const float2*)(b + lane * 2);
    float y0 = (v.x - m) * rs * gg.x + bb.x;
    float y1 = (v.y - m) * rs * gg.y + bb.y;
    __half h0 = __float2half(y0), h1 = __float2half(y1);
    __half l0 = __float2half(y0 - __half2float(h0));
    __half l1 = __float2half(y1 - __half2float(h1));
    uint32_t hw = ((uint32_t)__half_as_ushort(h1) << 16) | __half_as_ushort(h0);
    uint32_t lw = ((uint32_t)__half_as_ushort(l1) << 16) | __half_as_ushort(l0);
    *(uint32_t*)(pack + (size_t)w * 128 + lane * 2)      = hw;
    *(uint32_t*)(pack + (size_t)w * 128 + 64 + lane * 2) = lw;
}

__global__ void __launch_bounds__(256) k_ln128(const float* __restrict__ in,
                                               const float* __restrict__ g,
                                               const float* __restrict__ b,
                                               const float* __restrict__ res,
                                               float rscale, int doRelu,
                                               float* __restrict__ outf,
                                               __half* __restrict__ pack, int n) {
    int w = (blockIdx.x * 256 + threadIdx.x) >> 5;
    int lane = threadIdx.x & 31;
    if (w >= n) return;
    int c0 = lane * 4;
    float4 v = *(const float4*)(in + (size_t)w * 128 + c0);
    float s = v.x + v.y + v.z + v.w;
    float q = v.x * v.x + v.y * v.y + v.z * v.z + v.w * v.w;
    #pragma unroll
    for (int o = 16; o; o >>= 1) {
        s += __shfl_xor_sync(0xffffffffu, s, o);
        q += __shfl_xor_sync(0xffffffffu, q, o);
    }
    float m   = s * (1.f / 128.f);
    float var = q * (1.f / 128.f) - m * m;
    float rs  = rsqrtf(var + 1e-5f);
    float4 gg = *(const float4*)(g + c0);
    float4 bb = *(const float4*)(b + c0);
    float4 y;
    y.x = (v.x - m) * rs * gg.x + bb.x;
    y.y = (v.y - m) * rs * gg.y + bb.y;
    y.z = (v.z - m) * rs * gg.z + bb.z;
    y.w = (v.w - m) * rs * gg.w + bb.w;
    if (res) {
        float4 r4 = *(const float4*)(res + (size_t)w * 128 + c0);
        y.x += rscale * r4.x; y.y += rscale * r4.y;
        y.z += rscale * r4.z; y.w += rscale * r4.w;
    }
    if (doRelu) {
        y.x = fmaxf(y.x, 0.f); y.y = fmaxf(y.y, 0.f);
        y.z = fmaxf(y.z, 0.f); y.w = fmaxf(y.w, 0.f);
    }
    if (outf) *(float4*)(outf + (size_t)w * 128 + c0) = y;
    uint2 hi, lo;
    split4h(y, hi, lo);
    *(uint2*)(pack + (size_t)w * 256 + c0)       = hi;
    *(uint2*)(pack + (size_t)w * 256 + 128 + c0) = lo;
}

// ---------------- GATv2 aggregation: fp16 inputs, warp per dst node, online softmax ----------------
__device__ __forceinline__ float4 ld_half4(const __half* p) {
    uint2 raw = *(const uint2*)p;
    float2 a = __half22float2(*(__half2*)&raw.x);
    float2 b = __half22float2(*(__half2*)&raw.y);
    return make_float4(a.x, a.y, b.x, b.y);
}

__global__ void __launch_bounds__(256) k_agg(const __half* __restrict__ xl,
                                             const __half* __restrict__ xr,
                                             const float* __restrict__ att,
                                             float* __restrict__ out, int n, int grp) {
    int w = (blockIdx.x * 256 + threadIdx.x) >> 5;
    int lane = threadIdx.x & 31;
    if (w >= n) return;
    int c0 = lane * 4;
    float4 a4 = *(const float4*)(att + c0);
    float4 r4 = ld_half4(xr + (size_t)w * 128 + c0);
    int beg = g_row[w], deg = g_row[w + 1] - beg;
    float m = -1e30f, s = 0.f;
    float4 acc = make_float4(0.f, 0.f, 0.f, 0.f);

    auto logit = [&](float4 x) -> float {
        float e0 = x.x + r4.x, e1 = x.y + r4.y, e2 = x.z + r4.z, e3 = x.w + r4.w;
        e0 = (e0 > 0.f) ? e0 : 0.2f * e0;
        e1 = (e1 > 0.f) ? e1 : 0.2f * e1;
        e2 = (e2 > 0.f) ? e2 : 0.2f * e2;
        e3 = (e3 > 0.f) ? e3 : 0.2f * e3;
        return fmaf(a4.x, e0, fmaf(a4.y, e1, fmaf(a4.z, e2, a4.w * e3)));
    };

    int j = -1;                              // j == -1 is the self-loop
    for (; j + 1 < deg; j += 2) {
        int s0 = (j < 0) ? w : g_csrc[beg + j];
        int s1 = g_csrc[beg + j + 1];
        float4 x0 = ld_half4(xl + (size_t)s0 * 128 + c0);
        float4 x1 = ld_half4(xl + (size_t)s1 * 128 + c0);
        float p0 = logit(x0);
        float p1 = logit(x1);
        #pragma unroll
        for (int o = 1; o < 32; o <<= 1)
            if (o < grp) {
                p0 += __shfl_xor_sync(0xffffffffu, p0, o);
                p1 += __shfl_xor_sync(0xffffffffu, p1, o);
            }
        float mn = fmaxf(m, fmaxf(p0, p1));
        float sc = __expf(m - mn);
        float w0 = __expf(p0 - mn);
        float w1 = __expf(p1 - mn);
        s = fmaf(s, sc, w0 + w1);
        acc.x = fmaf(acc.x, sc, fmaf(w0, x0.x, w1 * x1.x));
        acc.y = fmaf(acc.y, sc, fmaf(w0, x0.y, w1 * x1.y));
        acc.z = fmaf(acc.z, sc, fmaf(w0, x0.z, w1 * x1.z));
        acc.w = fmaf(acc.w, sc, fmaf(w0, x0.w, w1 * x1.w));
        m = mn;
    }
    if (j < deg) {                           // leftover single edge (or lone self-loop)
        int s0 = (j < 0) ? w : g_csrc[beg + j];
        float4 x0 = ld_half4(xl + (size_t)s0 * 128 + c0);
        float p0 = logit(x0);
        #pragma unroll
        for (int o = 1; o < 32; o <<= 1)
            if (o < grp) p0 += __shfl_xor_sync(0xffffffffu, p0, o);
        float mn = fmaxf(m, p0);
        float sc = __expf(m - mn);
        float w0 = __expf(p0 - mn);
        s = fmaf(s, sc, w0);
        acc.x = fmaf(acc.x, sc, w0 * x0.x);
        acc.y = fmaf(acc.y, sc, w0 * x0.y);
        acc.z = fmaf(acc.z, sc, w0 * x0.z);
        acc.w = fmaf(acc.w, sc, w0 * x0.w);
        m = mn;
    }
    float inv = 1.f / s;
    float4 o4 = make_float4(acc.x * inv, acc.y * inv, acc.z * inv, acc.w * inv);
    *(float4*)(out + (size_t)w * 128 + c0) = o4;
}

// ---------------- prediction heads ----------------
__global__ void __launch_bounds__(256) k_head2(const float* __restrict__ T,
                                               const float* __restrict__ w2a,
                                               const float* __restrict__ b2a,
                                               const float* __restrict__ w2b,
                                               const float* __restrict__ b2b,
                                               float* __restrict__ out, int n) {
    int w = (blockIdx.x * 256 + threadIdx.x) >> 5;
    int lane = threadIdx.x & 31;
    if (w >= n) return;
    const float* t = T + (size_t)w * 128;
    float tA = fmaf(t[lane],      w2a[lane],      t[32 + lane] * w2a[32 + lane]);
    float tB = fmaf(t[64 + lane], w2b[lane],      t[96 + lane] * w2b[32 + lane]);
    #pragma unroll
    for (int o = 16; o; o >>= 1) {
        tA += __shfl_xor_sync(0xffffffffu, tA, o);
        tB += __shfl_xor_sync(0xffffffffu, tB, o);
    }
    if (lane == 0) {
        out[(size_t)2 * w]     = tA + b2a[0];
        out[(size_t)2 * w + 1] = tB + b2b[0];
    }
}

// ---------------- launch ----------------
extern "C" void kernel_launch(void* const* d_in, const int* in_sizes, int n_in,
                              void* d_out, int out_size) {
    const float* x       = (const float*)d_in[0];
    const int*   ei      = (const int*)  d_in[1];
    const float* ln_in_g = (const float*)d_in[2];
    const float* ln_in_b = (const float*)d_in[3];
    const float* w_l1    = (const float*)d_in[4];
    const float* w_r1    = (const float*)d_in[5];
    const float* att1    = (const float*)d_in[6];
    const float* ln1_g   = (const float*)d_in[7];
    const float* ln1_b   = (const float*)d_in[8];
    const float* w_l2    = (const float*)d_in[9];
    const float* w_r2    = (const float*)d_in[10];
    const float* att2    = (const float*)d_in[11];
    const float* ln2_g   = (const float*)d_in[12];
    const float* ln2_b   = (const float*)d_in[13];
    const float* w_l3    = (const float*)d_in[14];
    const float* w_r3    = (const float*)d_in[15];
    const float* att3    = (const float*)d_in[16];
    const float* ln3_g   = (const float*)d_in[17];
    const float* ln3_b   = (const float*)d_in[18];
    const float* rtt_w1  = (const float*)d_in[19];
    const float* rtt_b1  = (const float*)d_in[20];
    const float* rtt_w2  = (const float*)d_in[21];
    const float* rtt_b2  = (const float*)d_in[22];
    const float* ret_w1  = (const float*)d_in[23];
    const float* ret_b1  = (const float*)d_in[24];
    const float* ret_w2  = (const float*)d_in[25];
    const float* ret_b2  = (const float*)d_in[26];

    const int n = in_sizes[0] / 64;
    const int e = in_sizes[1] / 2;
    const int* srcv = ei;
    const int* dstv = ei + e;

    float *p_h, *p_xl, *p_xr, *p_gg, *p_b1;
    __half *p_pk, *p_W0, *p_W1, *p_W2, *p_WH;
    cudaGetSymbolAddress((void**)&p_h,  g_h);
    cudaGetSymbolAddress((void**)&p_xl, g_xl);
    cudaGetSymbolAddress((void**)&p_xr, g_xr);
    cudaGetSymbolAddress((void**)&p_gg, g_gg);
    cudaGetSymbolAddress((void**)&p_b1, g_b1cat);
    cudaGetSymbolAddress((void**)&p_pk, g_pk);
    cudaGetSymbolAddress((void**)&p_W0, g_W0);
    cudaGetSymbolAddress((void**)&p_W1, g_W1);
    cudaGetSymbolAddress((void**)&p_W2, g_W2);
    cudaGetSymbolAddress((void**)&p_WH, g_WH);
    __half* h_xl = (__half*)p_xl;
    __half* h_xr = (__half*)p_xr;

    const int NBn = (n + 255) / 256;
    const int EB  = (e + 255) / 256;
    const int WB  = (n + 7) / 8;
    const int GBx = (n + 127) / 128;
    dim3 GB256(GBx, 4);   // NT=256 -> 4 column blocks of 64
    dim3 GB128(GBx, 2);   // NT=128 -> 2 column blocks of 64

    const int SMEM = 3 * (128 * APAD * 2 + 64 * BPAD * 2);   // 82944
    cudaFuncSetAttribute((const void*)k_gemm_mma<64, 256, false, true>,
                         cudaFuncAttributeMaxDynamicSharedMemorySize, SMEM);
    cudaFuncSetAttribute((const void*)k_gemm_mma<128, 256, false, true>,
                         cudaFuncAttributeMaxDynamicSharedMemorySize, SMEM);
    cudaFuncSetAttribute((const void*)k_gemm_mma<128, 128, true, false>,
                         cudaFuncAttributeMaxDynamicSharedMemorySize, SMEM);

    cudaStream_t s2;
    cudaEvent_t evFork, evCSR, evW2;
    cudaStreamCreateWithFlags(&s2, cudaStreamNonBlocking);
    cudaEventCreateWithFlags(&evFork, cudaEventDisableTiming);
    cudaEventCreateWithFlags(&evCSR, cudaEventDisableTiming);
    cudaEventCreateWithFlags(&evW2, cudaEventDisableTiming);

    // --- main branch: minimal prologue before gemm0 ---
    k_ln64<<<WB, 256>>>(x, ln_in_g, ln_in_b, p_pk, n);
    k_convW<64, 256> <<<(64 * 256 + 255) / 256, 256>>>(w_l1, w_r1, p_W0);
    k_convW<128, 256><<<(128 * 256 + 255) / 256, 256>>>(w_l2, w_r2, p_W1);
    k_gemm_mma<64, 256, false, true><<<GB256, 256, SMEM>>>(p_pk, p_W0, p_xl, p_xr, nullptr, n);

    // --- side branch: CSR build + late weight conversions ---
    cudaEventRecord(evFork, 0);
    cudaStreamWaitEvent(s2, evFork, 0);
    k_zero   <<<NBn, 256, 0, s2>>>(n);
    k_count  <<<EB,  256, 0, s2>>>(dstv, e);
    k_scan_a <<<NBn, 256, 0, s2>>>(n);
    k_scan_b <<<1, NB_MAX, 0, s2>>>(NBn);
    k_scan_c <<<NBn, 256, 0, s2>>>(n, e);
    k_scatter<<<EB,  256, 0, s2>>>(srcv, dstv, e);
    k_sortcsr<<<NBn, 256, 0, s2>>>(n);
    cudaEventRecord(evCSR, s2);
    k_convW<128, 256><<<(128 * 256 + 255) / 256, 256, 0, s2>>>(w_l3, w_r3, p_W2);
    k_convW<128, 128><<<(128 * 128 + 255) / 256, 256, 0, s2>>>(rtt_w1, ret_w1, p_WH);
    k_biascat<<<1, 128, 0, s2>>>(rtt_b1, ret_b1);
    cudaEventRecord(evW2, s2);

    // --- layer 0 aggregation (needs CSR) ---
    cudaStreamWaitEvent(0, evCSR, 0);
    k_agg<<<WB, 256>>>(h_xl, h_xr, att1, p_gg, n, 8);
    k_ln128<<<WB, 256>>>(p_gg, ln1_g, ln1_b, nullptr, 0.f, 1, p_h, p_pk, n);

    // --- layer 1 ---
    k_gemm_mma<128, 256, false, true><<<GB256, 256, SMEM>>>(p_pk, p_W1, p_xl, p_xr, nullptr, n);
    k_agg<<<WB, 256>>>(h_xl, h_xr, att2, p_gg, n, 8);
    k_ln128<<<WB, 256>>>(p_gg, ln2_g, ln2_b, p_h, 0.1f, 1, p_h, p_pk, n);

    // --- layer 2 (needs W2 from side stream) ---
    cudaStreamWaitEvent(0, evW2, 0);
    k_gemm_mma<128, 256, false, true><<<GB256, 256, SMEM>>>(p_pk, p_W2, p_xl, p_xr, nullptr, n);
    k_agg<<<WB, 256>>>(h_xl, h_xr, att3, p_gg, n, 32);
    k_ln128<<<WB, 256>>>(p_gg, ln3_g, ln3_b, p_h, 0.1f, 0, nullptr, p_pk, n);

    // --- heads ---
    k_gemm_mma<128, 128, true, false><<<GB128, 256, SMEM>>>(p_pk, p_WH, p_xl, nullptr, p_b1, n);
    k_head2<<<WB, 256>>>(p_xl, rtt_w2, rtt_b2, ret_w2, ret_b2, (float*)d_out, n);
}

// round 15
// speedup vs baseline: 1.0661x; 1.0384x over previous
#include <cuda_runtime.h>
#include <cuda_fp16.h>
#include <cstdint>
#include <math.h>

#define NN 100000
#define EE 800000
#define NB_MAX 512

// ---------------- scratch (device globals; no cudaMalloc allowed) ----------------
__device__ int   g_cnt[NN];
__device__ int   g_row[NN + 1];
__device__ int   g_cur[NN];
__device__ int   g_bsum[NB_MAX];
__device__ int   g_csrc[EE];
__device__ float g_h [NN * 128];
__device__ float g_xl[NN * 128];     // holds fp16 xl (reinterpreted) or fp32 head output
__device__ float g_xr[NN * 128];     // holds fp16 xr (reinterpreted)
__device__ float g_gg[NN * 128];
__device__ float g_b1cat[128];
__device__ __half g_pk[NN * 256];       // activation pack: [hi(K) | lo(K)] fp16 per row
__device__ __half g_W0[64 * 256];       // layer0 weight image [K x 256] fp16
__device__ __half g_W1[128 * 256];      // layer1
__device__ __half g_W2[128 * 256];      // layer2
__device__ __half g_WH[128 * 128];      // head

// ---------------- mma helpers ----------------
__device__ __forceinline__ void ldsm4(uint32_t addr, uint32_t& r0, uint32_t& r1,
                                      uint32_t& r2, uint32_t& r3) {
    asm volatile("ldmatrix.sync.aligned.m8n8.x4.shared.b16 {%0,%1,%2,%3}, [%4];"
                 : "=r"(r0), "=r"(r1), "=r"(r2), "=r"(r3) : "r"(addr));
}
__device__ __forceinline__ void ldsm4t(uint32_t addr, uint32_t& r0, uint32_t& r1,
                                       uint32_t& r2, uint32_t& r3) {
    asm volatile("ldmatrix.sync.aligned.m8n8.x4.trans.shared.b16 {%0,%1,%2,%3}, [%4];"
                 : "=r"(r0), "=r"(r1), "=r"(r2), "=r"(r3) : "r"(addr));
}
__device__ __forceinline__ void mma_f16(float* c, const uint32_t* a, uint32_t b0, uint32_t b1) {
    asm volatile(
        "mma.sync.aligned.m16n8k16.row.col.f32.f16.f16.f32 "
        "{%0,%1,%2,%3},{%4,%5,%6,%7},{%8,%9},{%0,%1,%2,%3};"
        : "+f"(c[0]), "+f"(c[1]), "+f"(c[2]), "+f"(c[3])
        : "r"(a[0]), "r"(a[1]), "r"(a[2]), "r"(a[3]), "r"(b0), "r"(b1));
}
__device__ __forceinline__ void split4h(float4 v, uint2& hi, uint2& lo) {
    __half h0 = __float2half(v.x), h1 = __float2half(v.y);
    __half h2 = __float2half(v.z), h3 = __float2half(v.w);
    __half l0 = __float2half(v.x - __half2float(h0));
    __half l1 = __float2half(v.y - __half2float(h1));
    __half l2 = __float2half(v.z - __half2float(h2));
    __half l3 = __float2half(v.w - __half2float(h3));
    hi.x = ((uint32_t)__half_as_ushort(h1) << 16) | __half_as_ushort(h0);
    hi.y = ((uint32_t)__half_as_ushort(h3) << 16) | __half_as_ushort(h2);
    lo.x = ((uint32_t)__half_as_ushort(l1) << 16) | __half_as_ushort(l0);
    lo.y = ((uint32_t)__half_as_ushort(l3) << 16) | __half_as_ushort(l2);
}

// ---------------- weight pre-convert: fp32 [K x H] pair -> fp16 image [K x NT] ----------------
template <int K, int NT>
__global__ void k_convW(const float* __restrict__ Wl, const float* __restrict__ Wr,
                        __half* __restrict__ img) {
    int idx = blockIdx.x * blockDim.x + threadIdx.x;
    if (idx >= K * NT) return;
    int k = idx / NT, col = idx % NT;
    const int H = NT / 2;
    float v = (col < H) ? Wl[k * H + col] : Wr[k * H + col - H];
    img[idx] = __float2half(v);
}

__global__ void k_biascat(const float* __restrict__ b1a, const float* __restrict__ b1b) {
    int i = threadIdx.x;
    if (i < 64) { g_b1cat[i] = b1a[i]; g_b1cat[64 + i] = b1b[i]; }
}

// ---------------- HMMA GEMM: 128 rows x 64 cols, fp16, xl=2-term / xr=1-term ----------------
#define APAD 72
#define BPAD 72
template <int K, int NT, bool BIAS_RELU, bool HALF_OUT>
__global__ void __launch_bounds__(256, 2) k_gemm_mma(
    const __half* __restrict__ Apack,
    const __half* __restrict__ Wimg,
    float* __restrict__ out1, float* __restrict__ out2,
    const float* __restrict__ bias, int n)
{
    constexpr int C = 2 * K / 64;                 // full k-chunks: [hi chunks | lo chunks]
    constexpr int ABYTES = 128 * APAD * 2;        // 18432
    constexpr int BBYTES = 64 * BPAD * 2;         // 9216
    constexpr int STG = ABYTES + BBYTES;          // 27648 per stage
    constexpr int K2 = 2 * K;
    extern __shared__ char sm[];
    const uint32_t sbase = (uint32_t)__cvta_generic_to_shared(sm);
    const int tid = threadIdx.x, lane = tid & 31, wid = tid >> 5;
    const int wm = wid & 3, wn = wid >> 2;        // 4 warps M (32 rows), 2 warps N (32 cols)
    const int row0 = blockIdx.x * 128;
    const int col0 = blockIdx.y * 64;             // column block within NT

    // xr half (cols >= 128 of fused NT=256 GEMM) feeds only attention logits:
    // skip the lo-term chunks (hi-only), saving 50% of its MMA work.
    const bool hiOnly = (NT == 256) && (col0 >= 128);
    const int CC = hiOnly ? (C / 2) : C;

    auto loadChunk = [&](int c) {
        const int per = K / 64;
        const int t = c / per;                    // 0 = hi half, 1 = lo half
        const int within = c - t * per;
        const int a_off = t * K + within * 64;
        const int brow = within * 64;             // same W for both halves
        const uint32_t sA = sbase + (uint32_t)(c % 3) * STG;
        const uint32_t sB = sA + ABYTES;
        #pragma unroll
        for (int i = tid; i < 1024; i += 256) {                 // A: 128 x 64
            int r = i >> 3, cc = (i & 7) * 8;
            int grow = row0 + r; if (grow > n - 1) grow = n - 1;
            uint32_t dst = sA + (uint32_t)(r * APAD + cc) * 2;
            const __half* src = Apack + (size_t)grow * K2 + a_off + cc;
            asm volatile("cp.async.ca.shared.global [%0], [%1], 16;" :: "r"(dst), "l"(src));
        }
        #pragma unroll
        for (int i = tid; i < 512; i += 256) {                  // B: 64 x 64
            int r = i >> 3, cc = (i & 7) * 8;
            uint32_t dst = sB + (uint32_t)(r * BPAD + cc) * 2;
            const __half* src = Wimg + (size_t)(brow + r) * NT + col0 + cc;
            asm volatile("cp.async.ca.shared.global [%0], [%1], 16;" :: "r"(dst), "l"(src));
        }
        asm volatile("cp.async.commit_group;" ::: "memory");
    };

    float acc[2][4][4];
    #pragma unroll
    for (int i = 0; i < 2; i++)
        #pragma unroll
        for (int j = 0; j < 4; j++)
            #pragma unroll
            for (int q = 0; q < 4; q++) acc[i][j][q] = 0.f;

    loadChunk(0);
    if (CC > 1) loadChunk(1);

    for (int c = 0; c < CC; c++) {
        if (c < CC - 1) asm volatile("cp.async.wait_group 1;" ::: "memory");
        else            asm volatile("cp.async.wait_group 0;" ::: "memory");
        __syncthreads();
        if (c + 2 < CC) loadChunk(c + 2);
        const uint32_t sA = sbase + (uint32_t)(c % 3) * STG;
        const uint32_t sB = sA + ABYTES;
        #pragma unroll
        for (int ks = 0; ks < 4; ks++) {
            uint32_t a[2][4];
            #pragma unroll
            for (int mi = 0; mi < 2; mi++) {
                uint32_t addr = sA +
                    (uint32_t)((wm * 32 + mi * 16 + (lane & 15)) * APAD + ks * 16 + 8 * (lane >> 4)) * 2;
                ldsm4(addr, a[mi][0], a[mi][1], a[mi][2], a[mi][3]);
            }
            #pragma unroll
            for (int ng = 0; ng < 2; ng++) {
                uint32_t b0, b1, b2, b3;
                uint32_t addr = sB +
                    (uint32_t)((ks * 16 + (lane & 15)) * BPAD + wn * 32 + ng * 16 + 8 * (lane >> 4)) * 2;
                ldsm4t(addr, b0, b1, b2, b3);
                mma_f16(acc[0][ng * 2],     a[0], b0, b1);
                mma_f16(acc[0][ng * 2 + 1], a[0], b2, b3);
                mma_f16(acc[1][ng * 2],     a[1], b0, b1);
                mma_f16(acc[1][ng * 2 + 1], a[1], b2, b3);
            }
        }
    }

    // epilogue
    const int rb = row0 + wm * 32 + (lane >> 2);
    const int cbl = wn * 32 + (lane & 3) * 2;     // col within 64-wide block
    #pragma unroll
    for (int mi = 0; mi < 2; mi++) {
        #pragma unroll
        for (int ni = 0; ni < 4; ni++) {
            int col = col0 + cbl + ni * 8;        // global col within NT
            #pragma unroll
            for (int h = 0; h < 2; h++) {
                int rg = rb + mi * 16 + h * 8;
                if (rg < n) {
                    float2 v;
                    v.x = acc[mi][ni][h * 2 + 0];
                    v.y = acc[mi][ni][h * 2 + 1];
                    if (BIAS_RELU) {
                        v.x = fmaxf(v.x + bias[col], 0.f);
                        v.y = fmaxf(v.y + bias[col + 1], 0.f);
                    }
                    float* dst = out1;
                    int cc = col;
                    if (NT == 256 && col >= 128) { dst = out2; cc = col - 128; }
                    if (HALF_OUT) {
                        __half2 hv = __floats2half2_rn(v.x, v.y);
                        *(__half2*)((__half*)dst + (size_t)rg * 128 + cc) = hv;
                    } else {
                        *(float2*)(dst + (size_t)rg * 128 + cc) = v;
                    }
                }
            }
        }
    }
}

// ---------------- CSR build ----------------
__global__ void k_zero(int n) {
    int i = blockIdx.x * blockDim.x + threadIdx.x;
    if (i < n) g_cnt[i] = 0;
}

__global__ void k_count(const int* __restrict__ dstv, int e) {
    int i = blockIdx.x * blockDim.x + threadIdx.x;
    if (i < e) atomicAdd(&g_cnt[dstv[i]], 1);
}

__global__ void k_scan_a(int n) {
    __shared__ int sh[256];
    int i = blockIdx.x * 256 + threadIdx.x;
    int v = (i < n) ? g_cnt[i] : 0;
    sh[threadIdx.x] = v;
    __syncthreads();
    #pragma unroll
    for (int o = 1; o < 256; o <<= 1) {
        int t = (threadIdx.x >= o) ? sh[threadIdx.x - o] : 0;
        __syncthreads();
        sh[threadIdx.x] += t;
        __syncthreads();
    }
    if (i < n) g_row[i] = sh[threadIdx.x] - v;
    if (threadIdx.x == 255) g_bsum[blockIdx.x] = sh[255];
}

__global__ void k_scan_b(int nb) {
    __shared__ int sh[NB_MAX];
    int t = threadIdx.x;
    int v = (t < nb) ? g_bsum[t] : 0;
    sh[t] = v;
    __syncthreads();
    #pragma unroll
    for (int o = 1; o < NB_MAX; o <<= 1) {
        int u = (t >= o) ? sh[t - o] : 0;
        __syncthreads();
        sh[t] += u;
        __syncthreads();
    }
    if (t < nb) g_bsum[t] = sh[t] - v;
}

__global__ void k_scan_c(int n, int e) {
    int i = blockIdx.x * 256 + threadIdx.x;
    if (i < n) {
        int r = g_row[i] + g_bsum[blockIdx.x];
        g_row[i] = r;
        g_cur[i] = r;
    }
    if (i == 0) g_row[n] = e;
}

__global__ void k_scatter(const int* __restrict__ srcv, const int* __restrict__ dstv, int e) {
    int i = blockIdx.x * blockDim.x + threadIdx.x;
    if (i < e) {
        int pos = atomicAdd(&g_cur[dstv[i]], 1);
        g_csrc[pos] = srcv[i];
    }
}

__global__ void k_sortcsr(int n) {
    int i = blockIdx.x * blockDim.x + threadIdx.x;
    if (i >= n) return;
    int b = g_row[i], e2 = g_row[i + 1];
    for (int a = b + 1; a < e2; a++) {
        int v = g_csrc[a];
        int k = a;
        while (k > b && g_csrc[k - 1] > v) { g_csrc[k] = g_csrc[k - 1]; k--; }
        g_csrc[k] = v;
    }
}

// ---------------- LayerNorm kernels (write fp16 hi/lo pack for the GEMM) ----------------
__global__ void __launch_bounds__(256) k_ln64(const float* __restrict__ x,
                                              const float* __restrict__ g,
                                              const float* __restrict__ b,
                                              __half* __restrict__ pack, int n) {
    int w = (blockIdx.x * 256 + threadIdx.x) >> 5;
    int lane = threadIdx.x & 31;
    if (w >= n) return;
    float2 v = *(const float2*)(x + (size_t)w * 64 + lane * 2);
    float s = v.x + v.y;
    float q = v.x * v.x + v.y * v.y;
    #pragma unroll
    for (int o = 16; o; o >>= 1) {
        s += __shfl_xor_sync(0xffffffffu, s, o);
        q += __shfl_xor_sync(0xffffffffu, q, o);
    }
    float m  = s * (1.f / 64.f);
    float var = q * (1.f / 64.f) - m * m;
    float rs = rsqrtf(var + 1e-5f);
    float2 gg = *(const float2*)(g + lane * 2);
    float2 bb = *(const float2*)(b + lane * 2);
    float y0 = (v.x - m) * rs * gg.x + bb.x;
    float y1 = (v.y - m) * rs * gg.y + bb.y;
    __half h0 = __float2half(y0), h1 = __float2half(y1);
    __half l0 = __float2half(y0 - __half2float(h0));
    __half l1 = __float2half(y1 - __half2float(h1));
    uint32_t hw = ((uint32_t)__half_as_ushort(h1) << 16) | __half_as_ushort(h0);
    uint32_t lw = ((uint32_t)__half_as_ushort(l1) << 16) | __half_as_ushort(l0);
    *(uint32_t*)(pack + (size_t)w * 128 + lane * 2)      = hw;
    *(uint32_t*)(pack + (size_t)w * 128 + 64 + lane * 2) = lw;
}

__global__ void __launch_bounds__(256) k_ln128(const float* __restrict__ in,
                                               const float* __restrict__ g,
                                               const float* __restrict__ b,
                                               const float* __restrict__ res,
                                               float rscale, int doRelu,
                                               float* __restrict__ outf,
                                               __half* __restrict__ pack, int n) {
    int w = (blockIdx.x * 256 + threadIdx.x) >> 5;
    int lane = threadIdx.x & 31;
    if (w >= n) return;
    int c0 = lane * 4;
    float4 v = *(const float4*)(in + (size_t)w * 128 + c0);
    float s = v.x + v.y + v.z + v.w;
    float q = v.x * v.x + v.y * v.y + v.z * v.z + v.w * v.w;
    #pragma unroll
    for (int o = 16; o; o >>= 1) {
        s += __shfl_xor_sync(0xffffffffu, s, o);
        q += __shfl_xor_sync(0xffffffffu, q, o);
    }
    float m   = s * (1.f / 128.f);
    float var = q * (1.f / 128.f) - m * m;
    float rs  = rsqrtf(var + 1e-5f);
    float4 gg = *(const float4*)(g + c0);
    float4 bb = *(const float4*)(b + c0);
    float4 y;
    y.x = (v.x - m) * rs * gg.x + bb.x;
    y.y = (v.y - m) * rs * gg.y + bb.y;
    y.z = (v.z - m) * rs * gg.z + bb.z;
    y.w = (v.w - m) * rs * gg.w + bb.w;
    if (res) {
        float4 r4 = *(const float4*)(res + (size_t)w * 128 + c0);
        y.x += rscale * r4.x; y.y += rscale * r4.y;
        y.z += rscale * r4.z; y.w += rscale * r4.w;
    }
    if (doRelu) {
        y.x = fmaxf(y.x, 0.f); y.y = fmaxf(y.y, 0.f);
        y.z = fmaxf(y.z, 0.f); y.w = fmaxf(y.w, 0.f);
    }
    if (outf) *(float4*)(outf + (size_t)w * 128 + c0) = y;
    uint2 hi, lo;
    split4h(y, hi, lo);
    *(uint2*)(pack + (size_t)w * 256 + c0)       = hi;
    *(uint2*)(pack + (size_t)w * 256 + 128 + c0) = lo;
}

// ---------------- GATv2 aggregation: fp16 inputs, warp per dst node, online softmax ----------------
__device__ __forceinline__ float4 ld_half4(const __half* p) {
    uint2 raw = *(const uint2*)p;
    float2 a = __half22float2(*(__half2*)&raw.x);
    float2 b = __half22float2(*(__half2*)&raw.y);
    return make_float4(a.x, a.y, b.x, b.y);
}

__global__ void __launch_bounds__(256) k_agg(const __half* __restrict__ xl,
                                             const __half* __restrict__ xr,
                                             const float* __restrict__ att,
                                             float* __restrict__ out, int n, int grp) {
    int w = (blockIdx.x * 256 + threadIdx.x) >> 5;
    int lane = threadIdx.x & 31;
    if (w >= n) return;
    int c0 = lane * 4;
    float4 a4 = *(const float4*)(att + c0);
    float4 r4 = ld_half4(xr + (size_t)w * 128 + c0);
    int beg = g_row[w], deg = g_row[w + 1] - beg;
    float m = -1e30f, s = 0.f;
    float4 acc = make_float4(0.f, 0.f, 0.f, 0.f);

    auto logit = [&](float4 x) -> float {
        float e0 = x.x + r4.x, e1 = x.y + r4.y, e2 = x.z + r4.z, e3 = x.w + r4.w;
        e0 = (e0 > 0.f) ? e0 : 0.2f * e0;
        e1 = (e1 > 0.f) ? e1 : 0.2f * e1;
        e2 = (e2 > 0.f) ? e2 : 0.2f * e2;
        e3 = (e3 > 0.f) ? e3 : 0.2f * e3;
        return fmaf(a4.x, e0, fmaf(a4.y, e1, fmaf(a4.z, e2, a4.w * e3)));
    };

    int j = -1;                              // j == -1 is the self-loop
    for (; j + 1 < deg; j += 2) {
        int s0 = (j < 0) ? w : g_csrc[beg + j];
        int s1 = g_csrc[beg + j + 1];
        float4 x0 = ld_half4(xl + (size_t)s0 * 128 + c0);
        float4 x1 = ld_half4(xl + (size_t)s1 * 128 + c0);
        float p0 = logit(x0);
        float p1 = logit(x1);
        #pragma unroll
        for (int o = 1; o < 32; o <<= 1)
            if (o < grp) {
                p0 += __shfl_xor_sync(0xffffffffu, p0, o);
                p1 += __shfl_xor_sync(0xffffffffu, p1, o);
            }
        float mn = fmaxf(m, fmaxf(p0, p1));
        float sc = __expf(m - mn);
        float w0 = __expf(p0 - mn);
        float w1 = __expf(p1 - mn);
        s = fmaf(s, sc, w0 + w1);
        acc.x = fmaf(acc.x, sc, fmaf(w0, x0.x, w1 * x1.x));
        acc.y = fmaf(acc.y, sc, fmaf(w0, x0.y, w1 * x1.y));
        acc.z = fmaf(acc.z, sc, fmaf(w0, x0.z, w1 * x1.z));
        acc.w = fmaf(acc.w, sc, fmaf(w0, x0.w, w1 * x1.w));
        m = mn;
    }
    if (j < deg) {                           // leftover single edge (or lone self-loop)
        int s0 = (j < 0) ? w : g_csrc[beg + j];
        float4 x0 = ld_half4(xl + (size_t)s0 * 128 + c0);
        float p0 = logit(x0);
        #pragma unroll
        for (int o = 1; o < 32; o <<= 1)
            if (o < grp) p0 += __shfl_xor_sync(0xffffffffu, p0, o);
        float mn = fmaxf(m, p0);
        float sc = __expf(m - mn);
        float w0 = __expf(p0 - mn);
        s = fmaf(s, sc, w0);
        acc.x = fmaf(acc.x, sc, w0 * x0.x);
        acc.y = fmaf(acc.y, sc, w0 * x0.y);
        acc.z = fmaf(acc.z, sc, w0 * x0.z);
        acc.w = fmaf(acc.w, sc, w0 * x0.w);
        m = mn;
    }
    float inv = 1.f / s;
    float4 o4 = make_float4(acc.x * inv, acc.y * inv, acc.z * inv, acc.w * inv);
    *(float4*)(out + (size_t)w * 128 + c0) = o4;
}

// ---------------- prediction heads ----------------
__global__ void __launch_bounds__(256) k_head2(const float* __restrict__ T,
                                               const float* __restrict__ w2a,
                                               const float* __restrict__ b2a,
                                               const float* __restrict__ w2b,
                                               const float* __restrict__ b2b,
                                               float* __restrict__ out, int n) {
    int w = (blockIdx.x * 256 + threadIdx.x) >> 5;
    int lane = threadIdx.x & 31;
    if (w >= n) return;
    const float* t = T + (size_t)w * 128;
    float tA = fmaf(t[lane],      w2a[lane],      t[32 + lane] * w2a[32 + lane]);
    float tB = fmaf(t[64 + lane], w2b[lane],      t[96 + lane] * w2b[32 + lane]);
    #pragma unroll
    for (int o = 16; o; o >>= 1) {
        tA += __shfl_xor_sync(0xffffffffu, tA, o);
        tB += __shfl_xor_sync(0xffffffffu, tB, o);
    }
    if (lane == 0) {
        out[(size_t)2 * w]     = tA + b2a[0];
        out[(size_t)2 * w + 1] = tB + b2b[0];
    }
}

// ---------------- launch ----------------
extern "C" void kernel_launch(void* const* d_in, const int* in_sizes, int n_in,
                              void* d_out, int out_size) {
    const float* x       = (const float*)d_in[0];
    const int*   ei      = (const int*)  d_in[1];
    const float* ln_in_g = (const float*)d_in[2];
    const float* ln_in_b = (const float*)d_in[3];
    const float* w_l1    = (const float*)d_in[4];
    const float* w_r1    = (const float*)d_in[5];
    const float* att1    = (const float*)d_in[6];
    const float* ln1_g   = (const float*)d_in[7];
    const float* ln1_b   = (const float*)d_in[8];
    const float* w_l2    = (const float*)d_in[9];
    const float* w_r2    = (const float*)d_in[10];
    const float* att2    = (const float*)d_in[11];
    const float* ln2_g   = (const float*)d_in[12];
    const float* ln2_b   = (const float*)d_in[13];
    const float* w_l3    = (const float*)d_in[14];
    const float* w_r3    = (const float*)d_in[15];
    const float* att3    = (const float*)d_in[16];
    const float* ln3_g   = (const float*)d_in[17];
    const float* ln3_b   = (const float*)d_in[18];
    const float* rtt_w1  = (const float*)d_in[19];
    const float* rtt_b1  = (const float*)d_in[20];
    const float* rtt_w2  = (const float*)d_in[21];
    const float* rtt_b2  = (const float*)d_in[22];
    const float* ret_w1  = (const float*)d_in[23];
    const float* ret_b1  = (const float*)d_in[24];
    const float* ret_w2  = (const float*)d_in[25];
    const float* ret_b2  = (const float*)d_in[26];

    const int n = in_sizes[0] / 64;
    const int e = in_sizes[1] / 2;
    const int* srcv = ei;
    const int* dstv = ei + e;

    float *p_h, *p_xl, *p_xr, *p_gg, *p_b1;
    __half *p_pk, *p_W0, *p_W1, *p_W2, *p_WH;
    cudaGetSymbolAddress((void**)&p_h,  g_h);
    cudaGetSymbolAddress((void**)&p_xl, g_xl);
    cudaGetSymbolAddress((void**)&p_xr, g_xr);
    cudaGetSymbolAddress((void**)&p_gg, g_gg);
    cudaGetSymbolAddress((void**)&p_b1, g_b1cat);
    cudaGetSymbolAddress((void**)&p_pk, g_pk);
    cudaGetSymbolAddress((void**)&p_W0, g_W0);
    cudaGetSymbolAddress((void**)&p_W1, g_W1);
    cudaGetSymbolAddress((void**)&p_W2, g_W2);
    cudaGetSymbolAddress((void**)&p_WH, g_WH);
    __half* h_xl = (__half*)p_xl;
    __half* h_xr = (__half*)p_xr;

    const int NBn = (n + 255) / 256;
    const int EB  = (e + 255) / 256;
    const int WB  = (n + 7) / 8;
    const int GBx = (n + 127) / 128;
    dim3 GB256(GBx, 4);   // NT=256 -> 4 column blocks of 64
    dim3 GB128(GBx, 2);   // NT=128 -> 2 column blocks of 64

    const int SMEM = 3 * (128 * APAD * 2 + 64 * BPAD * 2);   // 82944
    cudaFuncSetAttribute((const void*)k_gemm_mma<64, 256, false, true>,
                         cudaFuncAttributeMaxDynamicSharedMemorySize, SMEM);
    cudaFuncSetAttribute((const void*)k_gemm_mma<128, 256, false, true>,
                         cudaFuncAttributeMaxDynamicSharedMemorySize, SMEM);
    cudaFuncSetAttribute((const void*)k_gemm_mma<128, 128, true, false>,
                         cudaFuncAttributeMaxDynamicSharedMemorySize, SMEM);

    cudaStream_t s2;
    cudaEvent_t evFork, evCSR, evW2;
    cudaStreamCreateWithFlags(&s2, cudaStreamNonBlocking);
    cudaEventCreateWithFlags(&evFork, cudaEventDisableTiming);
    cudaEventCreateWithFlags(&evCSR, cudaEventDisableTiming);
    cudaEventCreateWithFlags(&evW2, cudaEventDisableTiming);

    // --- main branch: minimal prologue before gemm0 ---
    k_ln64<<<WB, 256>>>(x, ln_in_g, ln_in_b, p_pk, n);
    k_convW<64, 256> <<<(64 * 256 + 255) / 256, 256>>>(w_l1, w_r1, p_W0);
    k_convW<128, 256><<<(128 * 256 + 255) / 256, 256>>>(w_l2, w_r2, p_W1);
    k_gemm_mma<64, 256, false, true><<<GB256, 256, SMEM>>>(p_pk, p_W0, p_xl, p_xr, nullptr, n);

    // --- side branch: CSR build + late weight conversions ---
    cudaEventRecord(evFork, 0);
    cudaStreamWaitEvent(s2, evFork, 0);
    k_zero   <<<NBn, 256, 0, s2>>>(n);
    k_count  <<<EB,  256, 0, s2>>>(dstv, e);
    k_scan_a <<<NBn, 256, 0, s2>>>(n);
    k_scan_b <<<1, NB_MAX, 0, s2>>>(NBn);
    k_scan_c <<<NBn, 256, 0, s2>>>(n, e);
    k_scatter<<<EB,  256, 0, s2>>>(srcv, dstv, e);
    k_sortcsr<<<NBn, 256, 0, s2>>>(n);
    cudaEventRecord(evCSR, s2);
    k_convW<128, 256><<<(128 * 256 + 255) / 256, 256, 0, s2>>>(w_l3, w_r3, p_W2);
    k_convW<128, 128><<<(128 * 128 + 255) / 256, 256, 0, s2>>>(rtt_w1, ret_w1, p_WH);
    k_biascat<<<1, 128, 0, s2>>>(rtt_b1, ret_b1);
    cudaEventRecord(evW2, s2);

    // --- layer 0 aggregation (needs CSR) ---
    cudaStreamWaitEvent(0, evCSR, 0);
    k_agg<<<WB, 256>>>(h_xl, h_xr, att1, p_gg, n, 8);
    k_ln128<<<WB, 256>>>(p_gg, ln1_g, ln1_b, nullptr, 0.f, 1, p_h, p_pk, n);

    // --- layer 1 ---
    k_gemm_mma<128, 256, false, true><<<GB256, 256, SMEM>>>(p_pk, p_W1, p_xl, p_xr, nullptr, n);
    k_agg<<<WB, 256>>>(h_xl, h_xr, att2, p_gg, n, 8);
    k_ln128<<<WB, 256>>>(p_gg, ln2_g, ln2_b, p_h, 0.1f, 1, p_h, p_pk, n);

    // --- layer 2 (needs W2 from side stream) ---
    cudaStreamWaitEvent(0, evW2, 0);
    k_gemm_mma<128, 256, false, true><<<GB256, 256, SMEM>>>(p_pk, p_W2, p_xl, p_xr, nullptr, n);
    k_agg<<<WB, 256>>>(h_xl, h_xr, att3, p_gg, n, 32);
    k_ln128<<<WB, 256>>>(p_gg, ln3_g, ln3_b, p_h, 0.1f, 0, nullptr, p_pk, n);

    // --- heads ---
    k_gemm_mma<128, 128, true, false><<<GB128, 256, SMEM>>>(p_pk, p_WH, p_xl, nullptr, p_b1, n);
    k_head2<<<WB, 256>>>(p_xl, rtt_w2, rtt_b2, ret_w2, ret_b2, (float*)d_out, n);
}

// round 16
// speedup vs baseline: 1.1341x; 1.0638x over previous
#include <cuda_runtime.h>
#include <cuda_fp16.h>
#include <cstdint>
#include <math.h>

#define NN 100000
#define EE 800000
#define NB_MAX 512

// ---------------- scratch (device globals; no cudaMalloc allowed) ----------------
__device__ int   g_cnt[NN];
__device__ int   g_row[NN + 1];
__device__ int   g_cur[NN];
__device__ int   g_bsum[NB_MAX];
__device__ int   g_csrc[EE];
__device__ float g_xl[NN * 128];     // holds fp16 xl (reinterpreted) or fp32 head output
__device__ float g_xr[NN * 128];     // holds fp16 xr (reinterpreted)
__device__ float g_gg[NN * 128];
__device__ float g_b1cat[128];
__device__ __half g_pk[NN * 256];       // activation pack: [hi(K) | lo(K)] fp16 per row
__device__ __half g_W0[64 * 256];       // layer0 weight image [K x 256] fp16
__device__ __half g_W1[128 * 256];      // layer1
__device__ __half g_W2[128 * 256];      // layer2
__device__ __half g_WH[128 * 128];      // head

// ---------------- mma helpers ----------------
__device__ __forceinline__ void ldsm4(uint32_t addr, uint32_t& r0, uint32_t& r1,
                                      uint32_t& r2, uint32_t& r3) {
    asm volatile("ldmatrix.sync.aligned.m8n8.x4.shared.b16 {%0,%1,%2,%3}, [%4];"
                 : "=r"(r0), "=r"(r1), "=r"(r2), "=r"(r3) : "r"(addr));
}
__device__ __forceinline__ void ldsm4t(uint32_t addr, uint32_t& r0, uint32_t& r1,
                                       uint32_t& r2, uint32_t& r3) {
    asm volatile("ldmatrix.sync.aligned.m8n8.x4.trans.shared.b16 {%0,%1,%2,%3}, [%4];"
                 : "=r"(r0), "=r"(r1), "=r"(r2), "=r"(r3) : "r"(addr));
}
__device__ __forceinline__ void mma_f16(float* c, const uint32_t* a, uint32_t b0, uint32_t b1) {
    asm volatile(
        "mma.sync.aligned.m16n8k16.row.col.f32.f16.f16.f32 "
        "{%0,%1,%2,%3},{%4,%5,%6,%7},{%8,%9},{%0,%1,%2,%3};"
        : "+f"(c[0]), "+f"(c[1]), "+f"(c[2]), "+f"(c[3])
        : "r"(a[0]), "r"(a[1]), "r"(a[2]), "r"(a[3]), "r"(b0), "r"(b1));
}
__device__ __forceinline__ void split4h(float4 v, uint2& hi, uint2& lo) {
    __half h0 = __float2half(v.x), h1 = __float2half(v.y);
    __half h2 = __float2half(v.z), h3 = __float2half(v.w);
    __half l0 = __float2half(v.x - __half2float(h0));
    __half l1 = __float2half(v.y - __half2float(h1));
    __half l2 = __float2half(v.z - __half2float(h2));
    __half l3 = __float2half(v.w - __half2float(h3));
    hi.x = ((uint32_t)__half_as_ushort(h1) << 16) | __half_as_ushort(h0);
    hi.y = ((uint32_t)__half_as_ushort(h3) << 16) | __half_as_ushort(h2);
    lo.x = ((uint32_t)__half_as_ushort(l1) << 16) | __half_as_ushort(l0);
    lo.y = ((uint32_t)__half_as_ushort(l3) << 16) | __half_as_ushort(l2);
}
__device__ __forceinline__ float4 ld_half4(const __half* p) {
    uint2 raw = *(const uint2*)p;
    float2 a = __half22float2(*(__half2*)&raw.x);
    float2 b = __half22float2(*(__half2*)&raw.y);
    return make_float4(a.x, a.y, b.x, b.y);
}

// ---------------- weight pre-convert: fp32 [K x H] pair -> fp16 image [K x NT] ----------------
template <int K, int NT>
__global__ void k_convW(const float* __restrict__ Wl, const float* __restrict__ Wr,
                        __half* __restrict__ img) {
    int idx = blockIdx.x * blockDim.x + threadIdx.x;
    if (idx >= K * NT) return;
    int k = idx / NT, col = idx % NT;
    const int H = NT / 2;
    float v = (col < H) ? Wl[k * H + col] : Wr[k * H + col - H];
    img[idx] = __float2half(v);
}

__global__ void k_biascat(const float* __restrict__ b1a, const float* __restrict__ b1b) {
    int i = threadIdx.x;
    if (i < 64) { g_b1cat[i] = b1a[i]; g_b1cat[64 + i] = b1b[i]; }
}

// ---------------- HMMA GEMM: 128 rows x 64 cols, fp16, xl=2-term / xr,head=1-term ----------------
#define APAD 72
#define BPAD 72
template <int K, int NT, bool BIAS_RELU, bool HALF_OUT, bool HI_ONLY_ALL>
__global__ void __launch_bounds__(256, 2) k_gemm_mma(
    const __half* __restrict__ Apack,
    const __half* __restrict__ Wimg,
    float* __restrict__ out1, float* __restrict__ out2,
    const float* __restrict__ bias, int n)
{
    constexpr int C = 2 * K / 64;                 // full k-chunks: [hi chunks | lo chunks]
    constexpr int ABYTES = 128 * APAD * 2;        // 18432
    constexpr int BBYTES = 64 * BPAD * 2;         // 9216
    constexpr int STG = ABYTES + BBYTES;          // 27648 per stage
    constexpr int K2 = 2 * K;
    extern __shared__ char sm[];
    const uint32_t sbase = (uint32_t)__cvta_generic_to_shared(sm);
    const int tid = threadIdx.x, lane = tid & 31, wid = tid >> 5;
    const int wm = wid & 3, wn = wid >> 2;        // 4 warps M (32 rows), 2 warps N (32 cols)
    const int row0 = blockIdx.x * 128;
    const int col0 = blockIdx.y * 64;             // column block within NT

    // hi-only (skip lo-term chunks): xr half of fused GEMMs (logit-only use),
    // or the whole kernel when HI_ONLY_ALL (prediction-head GEMM).
    const bool hiOnly = HI_ONLY_ALL || ((NT == 256) && (col0 >= 128));
    const int CC = hiOnly ? (C / 2) : C;

    auto loadChunk = [&](int c) {
        const int per = K / 64;
        const int t = c / per;                    // 0 = hi half, 1 = lo half
        const int within = c - t * per;
        const int a_off = t * K + within * 64;
        const int brow = within * 64;             // same W for both halves
        const uint32_t sA = sbase + (uint32_t)(c % 3) * STG;
        const uint32_t sB = sA + ABYTES;
        #pragma unroll
        for (int i = tid; i < 1024; i += 256) {                 // A: 128 x 64
            int r = i >> 3, cc = (i & 7) * 8;
            int grow = row0 + r; if (grow > n - 1) grow = n - 1;
            uint32_t dst = sA + (uint32_t)(r * APAD + cc) * 2;
            const __half* src = Apack + (size_t)grow * K2 + a_off + cc;
            asm volatile("cp.async.ca.shared.global [%0], [%1], 16;" :: "r"(dst), "l"(src));
        }
        #pragma unroll
        for (int i = tid; i < 512; i += 256) {                  // B: 64 x 64
            int r = i >> 3, cc = (i & 7) * 8;
            uint32_t dst = sB + (uint32_t)(r * BPAD + cc) * 2;
            const __half* src = Wimg + (size_t)(brow + r) * NT + col0 + cc;
            asm volatile("cp.async.ca.shared.global [%0], [%1], 16;" :: "r"(dst), "l"(src));
        }
        asm volatile("cp.async.commit_group;" ::: "memory");
    };

    float acc[2][4][4];
    #pragma unroll
    for (int i = 0; i < 2; i++)
        #pragma unroll
        for (int j = 0; j < 4; j++)
            #pragma unroll
            for (int q = 0; q < 4; q++) acc[i][j][q] = 0.f;

    loadChunk(0);
    if (CC > 1) loadChunk(1);

    for (int c = 0; c < CC; c++) {
        if (c < CC - 1) asm volatile("cp.async.wait_group 1;" ::: "memory");
        else            asm volatile("cp.async.wait_group 0;" ::: "memory");
        __syncthreads();
        if (c + 2 < CC) loadChunk(c + 2);
        const uint32_t sA = sbase + (uint32_t)(c % 3) * STG;
        const uint32_t sB = sA + ABYTES;
        #pragma unroll
        for (int ks = 0; ks < 4; ks++) {
            uint32_t a[2][4];
            #pragma unroll
            for (int mi = 0; mi < 2; mi++) {
                uint32_t addr = sA +
                    (uint32_t)((wm * 32 + mi * 16 + (lane & 15)) * APAD + ks * 16 + 8 * (lane >> 4)) * 2;
                ldsm4(addr, a[mi][0], a[mi][1], a[mi][2], a[mi][3]);
            }
            #pragma unroll
            for (int ng = 0; ng < 2; ng++) {
                uint32_t b0, b1, b2, b3;
                uint32_t addr = sB +
                    (uint32_t)((ks * 16 + (lane & 15)) * BPAD + wn * 32 + ng * 16 + 8 * (lane >> 4)) * 2;
                ldsm4t(addr, b0, b1, b2, b3);
                mma_f16(acc[0][ng * 2],     a[0], b0, b1);
                mma_f16(acc[0][ng * 2 + 1], a[0], b2, b3);
                mma_f16(acc[1][ng * 2],     a[1], b0, b1);
                mma_f16(acc[1][ng * 2 + 1], a[1], b2, b3);
            }
        }
    }

    // epilogue
    const int rb = row0 + wm * 32 + (lane >> 2);
    const int cbl = wn * 32 + (lane & 3) * 2;     // col within 64-wide block
    #pragma unroll
    for (int mi = 0; mi < 2; mi++) {
        #pragma unroll
        for (int ni = 0; ni < 4; ni++) {
            int col = col0 + cbl + ni * 8;        // global col within NT
            #pragma unroll
            for (int h = 0; h < 2; h++) {
                int rg = rb + mi * 16 + h * 8;
                if (rg < n) {
                    float2 v;
                    v.x = acc[mi][ni][h * 2 + 0];
                    v.y = acc[mi][ni][h * 2 + 1];
                    if (BIAS_RELU) {
                        v.x = fmaxf(v.x + bias[col], 0.f);
                        v.y = fmaxf(v.y + bias[col + 1], 0.f);
                    }
                    float* dst = out1;
                    int cc = col;
                    if (NT == 256 && col >= 128) { dst = out2; cc = col - 128; }
                    if (HALF_OUT) {
                        __half2 hv = __floats2half2_rn(v.x, v.y);
                        *(__half2*)((__half*)dst + (size_t)rg * 128 + cc) = hv;
                    } else {
                        *(float2*)(dst + (size_t)rg * 128 + cc) = v;
                    }
                }
            }
        }
    }
}

// ---------------- CSR build ----------------
__global__ void k_zero(int n) {
    int i = blockIdx.x * blockDim.x + threadIdx.x;
    if (i < n) g_cnt[i] = 0;
}

__global__ void k_count(const int* __restrict__ dstv, int e) {
    int i = blockIdx.x * blockDim.x + threadIdx.x;
    if (i < e) atomicAdd(&g_cnt[dstv[i]], 1);
}

__global__ void k_scan_a(int n) {
    __shared__ int sh[256];
    int i = blockIdx.x * 256 + threadIdx.x;
    int v = (i < n) ? g_cnt[i] : 0;
    sh[threadIdx.x] = v;
    __syncthreads();
    #pragma unroll
    for (int o = 1; o < 256; o <<= 1) {
        int t = (threadIdx.x >= o) ? sh[threadIdx.x - o] : 0;
        __syncthreads();
        sh[threadIdx.x] += t;
        __syncthreads();
    }
    if (i < n) g_row[i] = sh[threadIdx.x] - v;
    if (threadIdx.x == 255) g_bsum[blockIdx.x] = sh[255];
}

__global__ void k_scan_b(int nb) {
    __shared__ int sh[NB_MAX];
    int t = threadIdx.x;
    int v = (t < nb) ? g_bsum[t] : 0;
    sh[t] = v;
    __syncthreads();
    #pragma unroll
    for (int o = 1; o < NB_MAX; o <<= 1) {
        int u = (t >= o) ? sh[t - o] : 0;
        __syncthreads();
        sh[t] += u;
        __syncthreads();
    }
    if (t < nb) g_bsum[t] = sh[t] - v;
}

__global__ void k_scan_c(int n, int e) {
    int i = blockIdx.x * 256 + threadIdx.x;
    if (i < n) {
        int r = g_row[i] + g_bsum[blockIdx.x];
        g_row[i] = r;
        g_cur[i] = r;
    }
    if (i == 0) g_row[n] = e;
}

__global__ void k_scatter(const int* __restrict__ srcv, const int* __restrict__ dstv, int e) {
    int i = blockIdx.x * blockDim.x + threadIdx.x;
    if (i < e) {
        int pos = atomicAdd(&g_cur[dstv[i]], 1);
        g_csrc[pos] = srcv[i];
    }
}

__global__ void k_sortcsr(int n) {
    int i = blockIdx.x * blockDim.x + threadIdx.x;
    if (i >= n) return;
    int b = g_row[i], e2 = g_row[i + 1];
    for (int a = b + 1; a < e2; a++) {
        int v = g_csrc[a];
        int k = a;
        while (k > b && g_csrc[k - 1] > v) { g_csrc[k] = g_csrc[k - 1]; k--; }
        g_csrc[k] = v;
    }
}

// ---------------- LayerNorm kernels (write fp16 hi/lo pack for the GEMM) ----------------
__global__ void __launch_bounds__(256) k_ln64(const float* __restrict__ x,
                                              const float* __restrict__ g,
                                              const float* __restrict__ b,
                                              __half* __restrict__ pack, int n) {
    int w = (blockIdx.x * 256 + threadIdx.x) >> 5;
    int lane = threadIdx.x & 31;
    if (w >= n) return;
    float2 v = *(const float2*)(x + (size_t)w * 64 + lane * 2);
    float s = v.x + v.y;
    float q = v.x * v.x + v.y * v.y;
    #pragma unroll
    for (int o = 16; o; o >>= 1) {
        s += __shfl_xor_sync(0xffffffffu, s, o);
        q += __shfl_xor_sync(0xffffffffu, q, o);
    }
    float m  = s * (1.f / 64.f);
    float var = q * (1.f / 64.f) - m * m;
    float rs = rsqrtf(var + 1e-5f);
    float2 gg = *(const float2*)(g + lane * 2);
    float2 bb = *(const float2*)(b + lane * 2);
    float y0 = (v.x - m) * rs * gg.x + bb.x;
    float y1 = (v.y - m) * rs * gg.y + bb.y;
    __half h0 = __float2half(y0), h1 = __float2half(y1);
    __half l0 = __float2half(y0 - __half2float(h0));
    __half l1 = __float2half(y1 - __half2float(h1));
    uint32_t hw = ((uint32_t)__half_as_ushort(h1) << 16) | __half_as_ushort(h0);
    uint32_t lw = ((uint32_t)__half_as_ushort(l1) << 16) | __half_as_ushort(l0);
    *(uint32_t*)(pack + (size_t)w * 128 + lane * 2)      = hw;
    *(uint32_t*)(pack + (size_t)w * 128 + 64 + lane * 2) = lw;
}

// LayerNorm + residual(from old pack hi) + relu + repack.
// Residual h_{i} == hi-half of the pack written by the previous ln (read before overwrite).
__global__ void __launch_bounds__(256) k_ln128(const float* __restrict__ in,
                                               const float* __restrict__ g,
                                               const float* __restrict__ b,
                                               int useRes, float rscale, int doRelu,
                                               __half* __restrict__ pack, int n) {
    int w = (blockIdx.x * 256 + threadIdx.x) >> 5;
    int lane = threadIdx.x & 31;
    if (w >= n) return;
    int c0 = lane * 4;
    float4 res4 = make_float4(0.f, 0.f, 0.f, 0.f);
    if (useRes) res4 = ld_half4(pack + (size_t)w * 256 + c0);   // old hi-half = previous h
    float4 v = *(const float4*)(in + (size_t)w * 128 + c0);
    float s = v.x + v.y + v.z + v.w;
    float q = v.x * v.x + v.y * v.y + v.z * v.z + v.w * v.w;
    #pragma unroll
    for (int o = 16; o; o >>= 1) {
        s += __shfl_xor_sync(0xffffffffu, s, o);
        q += __shfl_xor_sync(0xffffffffu, q, o);
    }
    float m   = s * (1.f / 128.f);
    float var = q * (1.f / 128.f) - m * m;
    float rs  = rsqrtf(var + 1e-5f);
    float4 gg = *(const float4*)(g + c0);
    float4 bb = *(const float4*)(b + c0);
    float4 y;
    y.x = (v.x - m) * rs * gg.x + bb.x;
    y.y = (v.y - m) * rs * gg.y + bb.y;
    y.z = (v.z - m) * rs * gg.z + bb.z;
    y.w = (v.w - m) * rs * gg.w + bb.w;
    if (useRes) {
        y.x += rscale * res4.x; y.y += rscale * res4.y;
        y.z += rscale * res4.z; y.w += rscale * res4.w;
    }
    if (doRelu) {
        y.x = fmaxf(y.x, 0.f); y.y = fmaxf(y.y, 0.f);
        y.z = fmaxf(y.z, 0.f); y.w = fmaxf(y.w, 0.f);
    }
    uint2 hi, lo;
    split4h(y, hi, lo);
    *(uint2*)(pack + (size_t)w * 256 + c0)       = hi;
    *(uint2*)(pack + (size_t)w * 256 + 128 + c0) = lo;
}

// ---------------- GATv2 aggregation: fp16 inputs, warp per dst node, online softmax ----------------
__global__ void __launch_bounds__(256) k_agg(const __half* __restrict__ xl,
                                             const __half* __restrict__ xr,
                                             const float* __restrict__ att,
                                             float* __restrict__ out, int n, int grp) {
    int w = (blockIdx.x * 256 + threadIdx.x) >> 5;
    int lane = threadIdx.x & 31;
    if (w >= n) return;
    int c0 = lane * 4;
    float4 a4 = *(const float4*)(att + c0);
    float4 r4 = ld_half4(xr + (size_t)w * 128 + c0);
    int beg = g_row[w], deg = g_row[w + 1] - beg;
    float m = -1e30f, s = 0.f;
    float4 acc = make_float4(0.f, 0.f, 0.f, 0.f);

    auto logit = [&](float4 x) -> float {
        float e0 = x.x + r4.x, e1 = x.y + r4.y, e2 = x.z + r4.z, e3 = x.w + r4.w;
        e0 = (e0 > 0.f) ? e0 : 0.2f * e0;
        e1 = (e1 > 0.f) ? e1 : 0.2f * e1;
        e2 = (e2 > 0.f) ? e2 : 0.2f * e2;
        e3 = (e3 > 0.f) ? e3 : 0.2f * e3;
        return fmaf(a4.x, e0, fmaf(a4.y, e1, fmaf(a4.z, e2, a4.w * e3)));
    };

    int j = -1;                              // j == -1 is the self-loop
    for (; j + 1 < deg; j += 2) {
        int s0 = (j < 0) ? w : g_csrc[beg + j];
        int s1 = g_csrc[beg + j + 1];
        float4 x0 = ld_half4(xl + (size_t)s0 * 128 + c0);
        float4 x1 = ld_half4(xl + (size_t)s1 * 128 + c0);
        float p0 = logit(x0);
        float p1 = logit(x1);
        #pragma unroll
        for (int o = 1; o < 32; o <<= 1)
            if (o < grp) {
                p0 += __shfl_xor_sync(0xffffffffu, p0, o);
                p1 += __shfl_xor_sync(0xffffffffu, p1, o);
            }
        float mn = fmaxf(m, fmaxf(p0, p1));
        float sc = __expf(m - mn);
        float w0 = __expf(p0 - mn);
        float w1 = __expf(p1 - mn);
        s = fmaf(s, sc, w0 + w1);
        acc.x = fmaf(acc.x, sc, fmaf(w0, x0.x, w1 * x1.x));
        acc.y = fmaf(acc.y, sc, fmaf(w0, x0.y, w1 * x1.y));
        acc.z = fmaf(acc.z, sc, fmaf(w0, x0.z, w1 * x1.z));
        acc.w = fmaf(acc.w, sc, fmaf(w0, x0.w, w1 * x1.w));
        m = mn;
    }
    if (j < deg) {                           // leftover single edge (or lone self-loop)
        int s0 = (j < 0) ? w : g_csrc[beg + j];
        float4 x0 = ld_half4(xl + (size_t)s0 * 128 + c0);
        float p0 = logit(x0);
        #pragma unroll
        for (int o = 1; o < 32; o <<= 1)
            if (o < grp) p0 += __shfl_xor_sync(0xffffffffu, p0, o);
        float mn = fmaxf(m, p0);
        float sc = __expf(m - mn);
        float w0 = __expf(p0 - mn);
        s = fmaf(s, sc, w0);
        acc.x = fmaf(acc.x, sc, w0 * x0.x);
        acc.y = fmaf(acc.y, sc, w0 * x0.y);
        acc.z = fmaf(acc.z, sc, w0 * x0.z);
        acc.w = fmaf(acc.w, sc, w0 * x0.w);
        m = mn;
    }
    float inv = 1.f / s;
    float4 o4 = make_float4(acc.x * inv, acc.y * inv, acc.z * inv, acc.w * inv);
    *(float4*)(out + (size_t)w * 128 + c0) = o4;
}

// ---------------- prediction heads ----------------
__global__ void __launch_bounds__(256) k_head2(const float* __restrict__ T,
                                               const float* __restrict__ w2a,
                                               const float* __restrict__ b2a,
                                               const float* __restrict__ w2b,
                                               const float* __restrict__ b2b,
                                               float* __restrict__ out, int n) {
    int w = (blockIdx.x * 256 + threadIdx.x) >> 5;
    int lane = threadIdx.x & 31;
    if (w >= n) return;
    const float* t = T + (size_t)w * 128;
    float tA = fmaf(t[lane],      w2a[lane],      t[32 + lane] * w2a[32 + lane]);
    float tB = fmaf(t[64 + lane], w2b[lane],      t[96 + lane] * w2b[32 + lane]);
    #pragma unroll
    for (int o = 16; o; o >>= 1) {
        tA += __shfl_xor_sync(0xffffffffu, tA, o);
        tB += __shfl_xor_sync(0xffffffffu, tB, o);
    }
    if (lane == 0) {
        out[(size_t)2 * w]     = tA + b2a[0];
        out[(size_t)2 * w + 1] = tB + b2b[0];
    }
}

// ---------------- launch ----------------
extern "C" void kernel_launch(void* const* d_in, const int* in_sizes, int n_in,
                              void* d_out, int out_size) {
    const float* x       = (const float*)d_in[0];
    const int*   ei      = (const int*)  d_in[1];
    const float* ln_in_g = (const float*)d_in[2];
    const float* ln_in_b = (const float*)d_in[3];
    const float* w_l1    = (const float*)d_in[4];
    const float* w_r1    = (const float*)d_in[5];
    const float* att1    = (const float*)d_in[6];
    const float* ln1_g   = (const float*)d_in[7];
    const float* ln1_b   = (const float*)d_in[8];
    const float* w_l2    = (const float*)d_in[9];
    const float* w_r2    = (const float*)d_in[10];
    const float* att2    = (const float*)d_in[11];
    const float* ln2_g   = (const float*)d_in[12];
    const float* ln2_b   = (const float*)d_in[13];
    const float* w_l3    = (const float*)d_in[14];
    const float* w_r3    = (const float*)d_in[15];
    const float* att3    = (const float*)d_in[16];
    const float* ln3_g   = (const float*)d_in[17];
    const float* ln3_b   = (const float*)d_in[18];
    const float* rtt_w1  = (const float*)d_in[19];
    const float* rtt_b1  = (const float*)d_in[20];
    const float* rtt_w2  = (const float*)d_in[21];
    const float* rtt_b2  = (const float*)d_in[22];
    const float* ret_w1  = (const float*)d_in[23];
    const float* ret_b1  = (const float*)d_in[24];
    const float* ret_w2  = (const float*)d_in[25];
    const float* ret_b2  = (const float*)d_in[26];

    const int n = in_sizes[0] / 64;
    const int e = in_sizes[1] / 2;
    const int* srcv = ei;
    const int* dstv = ei + e;

    float *p_xl, *p_xr, *p_gg, *p_b1;
    __half *p_pk, *p_W0, *p_W1, *p_W2, *p_WH;
    cudaGetSymbolAddress((void**)&p_xl, g_xl);
    cudaGetSymbolAddress((void**)&p_xr, g_xr);
    cudaGetSymbolAddress((void**)&p_gg, g_gg);
    cudaGetSymbolAddress((void**)&p_b1, g_b1cat);
    cudaGetSymbolAddress((void**)&p_pk, g_pk);
    cudaGetSymbolAddress((void**)&p_W0, g_W0);
    cudaGetSymbolAddress((void**)&p_W1, g_W1);
    cudaGetSymbolAddress((void**)&p_W2, g_W2);
    cudaGetSymbolAddress((void**)&p_WH, g_WH);
    __half* h_xl = (__half*)p_xl;
    __half* h_xr = (__half*)p_xr;

    const int NBn = (n + 255) / 256;
    const int EB  = (e + 255) / 256;
    const int WB  = (n + 7) / 8;
    const int GBx = (n + 127) / 128;
    dim3 GB256(GBx, 4);   // NT=256 -> 4 column blocks of 64
    dim3 GB128(GBx, 2);   // NT=128 -> 2 column blocks of 64

    const int SMEM = 3 * (128 * APAD * 2 + 64 * BPAD * 2);   // 82944
    cudaFuncSetAttribute((const void*)k_gemm_mma<64, 256, false, true, false>,
                         cudaFuncAttributeMaxDynamicSharedMemorySize, SMEM);
    cudaFuncSetAttribute((const void*)k_gemm_mma<128, 256, false, true, false>,
                         cudaFuncAttributeMaxDynamicSharedMemorySize, SMEM);
    cudaFuncSetAttribute((const void*)k_gemm_mma<128, 128, true, false, true>,
                         cudaFuncAttributeMaxDynamicSharedMemorySize, SMEM);

    cudaStream_t s2;
    cudaEvent_t evFork, evCSR, evW2;
    cudaStreamCreateWithFlags(&s2, cudaStreamNonBlocking);
    cudaEventCreateWithFlags(&evFork, cudaEventDisableTiming);
    cudaEventCreateWithFlags(&evCSR, cudaEventDisableTiming);
    cudaEventCreateWithFlags(&evW2, cudaEventDisableTiming);

    // --- main branch: minimal prologue before gemm0 ---
    k_ln64<<<WB, 256>>>(x, ln_in_g, ln_in_b, p_pk, n);
    k_convW<64, 256> <<<(64 * 256 + 255) / 256, 256>>>(w_l1, w_r1, p_W0);
    k_convW<128, 256><<<(128 * 256 + 255) / 256, 256>>>(w_l2, w_r2, p_W1);
    k_gemm_mma<64, 256, false, true, false><<<GB256, 256, SMEM>>>(p_pk, p_W0, p_xl, p_xr, nullptr, n);

    // --- side branch: CSR build + late weight conversions ---
    cudaEventRecord(evFork, 0);
    cudaStreamWaitEvent(s2, evFork, 0);
    k_zero   <<<NBn, 256, 0, s2>>>(n);
    k_count  <<<EB,  256, 0, s2>>>(dstv, e);
    k_scan_a <<<NBn, 256, 0, s2>>>(n);
    k_scan_b <<<1, NB_MAX, 0, s2>>>(NBn);
    k_scan_c <<<NBn, 256, 0, s2>>>(n, e);
    k_scatter<<<EB,  256, 0, s2>>>(srcv, dstv, e);
    k_sortcsr<<<NBn, 256, 0, s2>>>(n);
    cudaEventRecord(evCSR, s2);
    k_convW<128, 256><<<(128 * 256 + 255) / 256, 256, 0, s2>>>(w_l3, w_r3, p_W2);
    k_convW<128, 128><<<(128 * 128 + 255) / 256, 256, 0, s2>>>(rtt_w1, ret_w1, p_WH);
    k_biascat<<<1, 128, 0, s2>>>(rtt_b1, ret_b1);
    cudaEventRecord(evW2, s2);

    // --- layer 0 aggregation (needs CSR) ---
    cudaStreamWaitEvent(0, evCSR, 0);
    k_agg<<<WB, 256>>>(h_xl, h_xr, att1, p_gg, n, 8);
    k_ln128<<<WB, 256>>>(p_gg, ln1_g, ln1_b, 0, 0.f, 1, p_pk, n);

    // --- layer 1 (residual = old pack hi) ---
    k_gemm_mma<128, 256, false, true, false><<<GB256, 256, SMEM>>>(p_pk, p_W1, p_xl, p_xr, nullptr, n);
    k_agg<<<WB, 256>>>(h_xl, h_xr, att2, p_gg, n, 8);
    k_ln128<<<WB, 256>>>(p_gg, ln2_g, ln2_b, 1, 0.1f, 1, p_pk, n);

    // --- layer 2 (needs W2 from side stream; residual = old pack hi) ---
    cudaStreamWaitEvent(0, evW2, 0);
    k_gemm_mma<128, 256, false, true, false><<<GB256, 256, SMEM>>>(p_pk, p_W2, p_xl, p_xr, nullptr, n);
    k_agg<<<WB, 256>>>(h_xl, h_xr, att3, p_gg, n, 32);
    k_ln128<<<WB, 256>>>(p_gg, ln3_g, ln3_b, 1, 0.1f, 0, p_pk, n);

    // --- heads (hi-only GEMM) ---
    k_gemm_mma<128, 128, true, false, true><<<GB128, 256, SMEM>>>(p_pk, p_WH, p_xl, nullptr, p_b1, n);
    k_head2<<<WB, 256>>>(p_xl, rtt_w2, rtt_b2, ret_w2, ret_b2, (float*)d_out, n);
}

// round 17
// speedup vs baseline: 1.1444x; 1.0091x over previous
#include <cuda_runtime.h>
#include <cuda_fp16.h>
#include <cstdint>
#include <math.h>

#define NN 100000
#define EE 800000
#define NB_MAX 512

// ---------------- scratch (device globals; no cudaMalloc allowed) ----------------
__device__ int   g_cnt[NN];
__device__ int   g_row[NN + 1];
__device__ int   g_cur[NN];
__device__ int   g_bsum[NB_MAX];
__device__ int   g_csrc[EE];
__device__ float g_xl[NN * 128];     // holds fp16 xl (reinterpreted)
__device__ float g_xr[NN * 128];     // holds fp16 xr (reinterpreted)
__device__ float g_gg[NN * 128];
__device__ float g_b1cat[128];
__device__ float g_w2cat[128];
__device__ float g_b2[2];
__device__ __half g_pk[NN * 256];       // activation pack: [hi(K) | lo(K)] fp16 per row
__device__ __half g_W0[64 * 256];       // layer0 weight image [K x 256] fp16
__device__ __half g_W1[128 * 256];      // layer1
__device__ __half g_W2[128 * 256];      // layer2
__device__ __half g_WH[128 * 128];      // head

// ---------------- mma helpers ----------------
__device__ __forceinline__ void ldsm4(uint32_t addr, uint32_t& r0, uint32_t& r1,
                                      uint32_t& r2, uint32_t& r3) {
    asm volatile("ldmatrix.sync.aligned.m8n8.x4.shared.b16 {%0,%1,%2,%3}, [%4];"
                 : "=r"(r0), "=r"(r1), "=r"(r2), "=r"(r3) : "r"(addr));
}
__device__ __forceinline__ void ldsm4t(uint32_t addr, uint32_t& r0, uint32_t& r1,
                                       uint32_t& r2, uint32_t& r3) {
    asm volatile("ldmatrix.sync.aligned.m8n8.x4.trans.shared.b16 {%0,%1,%2,%3}, [%4];"
                 : "=r"(r0), "=r"(r1), "=r"(r2), "=r"(r3) : "r"(addr));
}
__device__ __forceinline__ void mma_f16(float* c, const uint32_t* a, uint32_t b0, uint32_t b1) {
    asm volatile(
        "mma.sync.aligned.m16n8k16.row.col.f32.f16.f16.f32 "
        "{%0,%1,%2,%3},{%4,%5,%6,%7},{%8,%9},{%0,%1,%2,%3};"
        : "+f"(c[0]), "+f"(c[1]), "+f"(c[2]), "+f"(c[3])
        : "r"(a[0]), "r"(a[1]), "r"(a[2]), "r"(a[3]), "r"(b0), "r"(b1));
}
__device__ __forceinline__ void split4h(float4 v, uint2& hi, uint2& lo) {
    __half h0 = __float2half(v.x), h1 = __float2half(v.y);
    __half h2 = __float2half(v.z), h3 = __float2half(v.w);
    __half l0 = __float2half(v.x - __half2float(h0));
    __half l1 = __float2half(v.y - __half2float(h1));
    __half l2 = __float2half(v.z - __half2float(h2));
    __half l3 = __float2half(v.w - __half2float(h3));
    hi.x = ((uint32_t)__half_as_ushort(h1) << 16) | __half_as_ushort(h0);
    hi.y = ((uint32_t)__half_as_ushort(h3) << 16) | __half_as_ushort(h2);
    lo.x = ((uint32_t)__half_as_ushort(l1) << 16) | __half_as_ushort(l0);
    lo.y = ((uint32_t)__half_as_ushort(l3) << 16) | __half_as_ushort(l2);
}
__device__ __forceinline__ float4 ld_half4(const __half* p) {
    uint2 raw = *(const uint2*)p;
    float2 a = __half22float2(*(__half2*)&raw.x);
    float2 b = __half22float2(*(__half2*)&raw.y);
    return make_float4(a.x, a.y, b.x, b.y);
}

// ---------------- weight pre-convert: fp32 [K x H] pair -> fp16 image [K x NT] ----------------
template <int K, int NT>
__global__ void k_convW(const float* __restrict__ Wl, const float* __restrict__ Wr,
                        __half* __restrict__ img) {
    int idx = blockIdx.x * blockDim.x + threadIdx.x;
    if (idx >= K * NT) return;
    int k = idx / NT, col = idx % NT;
    const int H = NT / 2;
    float v = (col < H) ? Wl[k * H + col] : Wr[k * H + col - H];
    img[idx] = __float2half(v);
}

__global__ void k_biascat(const float* __restrict__ b1a, const float* __restrict__ b1b,
                          const float* __restrict__ w2a, const float* __restrict__ w2b,
                          const float* __restrict__ b2a, const float* __restrict__ b2b) {
    int i = threadIdx.x;
    if (i < 64) {
        g_b1cat[i] = b1a[i];  g_b1cat[64 + i] = b1b[i];
        g_w2cat[i] = w2a[i];  g_w2cat[64 + i] = w2b[i];
    }
    if (i == 0) { g_b2[0] = b2a[0]; g_b2[1] = b2b[0]; }
}

// ---- HMMA GEMM: 128 rows x 64 cols, fp16, xl=2-term / xr=1-term; optional fused head ----
#define APAD 72
#define BPAD 72
template <int K, int NT, bool BIAS_RELU, bool HALF_OUT, bool HEAD_FUSE>
__global__ void __launch_bounds__(256, 2) k_gemm_mma(
    const __half* __restrict__ Apack,
    const __half* __restrict__ Wimg,
    float* __restrict__ out1, float* __restrict__ out2,
    const float* __restrict__ bias,
    const float* __restrict__ w2cat, const float* __restrict__ b2v, int n)
{
    constexpr int C = 2 * K / 64;                 // full k-chunks: [hi chunks | lo chunks]
    constexpr int ABYTES = 128 * APAD * 2;        // 18432
    constexpr int BBYTES = 64 * BPAD * 2;         // 9216
    constexpr int STG = ABYTES + BBYTES;          // 27648 per stage
    constexpr int K2 = 2 * K;
    extern __shared__ char sm[];
    const uint32_t sbase = (uint32_t)__cvta_generic_to_shared(sm);
    const int tid = threadIdx.x, lane = tid & 31, wid = tid >> 5;
    const int wm = wid & 3, wn = wid >> 2;        // 4 warps M (32 rows), 2 warps N (32 cols)
    const int row0 = blockIdx.x * 128;
    const int col0 = blockIdx.y * 64;             // column block within NT

    // xr half of fused NT=256 GEMMs feeds only attention logits -> hi-only.
    const bool hiOnly = (NT == 256) && (col0 >= 128);
    const int CC = hiOnly ? (C / 2) : C;

    auto loadChunk = [&](int c) {
        const int per = K / 64;
        const int t = c / per;                    // 0 = hi half, 1 = lo half
        const int within = c - t * per;
        const int a_off = t * K + within * 64;
        const int brow = within * 64;             // same W for both halves
        const uint32_t sA = sbase + (uint32_t)(c % 3) * STG;
        const uint32_t sB = sA + ABYTES;
        #pragma unroll
        for (int i = tid; i < 1024; i += 256) {                 // A: 128 x 64
            int r = i >> 3, cc = (i & 7) * 8;
            int grow = row0 + r; if (grow > n - 1) grow = n - 1;
            uint32_t dst = sA + (uint32_t)(r * APAD + cc) * 2;
            const __half* src = Apack + (size_t)grow * K2 + a_off + cc;
            asm volatile("cp.async.ca.shared.global [%0], [%1], 16;" :: "r"(dst), "l"(src));
        }
        #pragma unroll
        for (int i = tid; i < 512; i += 256) {                  // B: 64 x 64
            int r = i >> 3, cc = (i & 7) * 8;
            uint32_t dst = sB + (uint32_t)(r * BPAD + cc) * 2;
            const __half* src = Wimg + (size_t)(brow + r) * NT + col0 + cc;
            asm volatile("cp.async.ca.shared.global [%0], [%1], 16;" :: "r"(dst), "l"(src));
        }
        asm volatile("cp.async.commit_group;" ::: "memory");
    };

    float acc[2][4][4];
    #pragma unroll
    for (int i = 0; i < 2; i++)
        #pragma unroll
        for (int j = 0; j < 4; j++)
            #pragma unroll
            for (int q = 0; q < 4; q++) acc[i][j][q] = 0.f;

    loadChunk(0);
    if (CC > 1) loadChunk(1);

    for (int c = 0; c < CC; c++) {
        if (c < CC - 1) asm volatile("cp.async.wait_group 1;" ::: "memory");
        else            asm volatile("cp.async.wait_group 0;" ::: "memory");
        __syncthreads();
        if (c + 2 < CC) loadChunk(c + 2);
        const uint32_t sA = sbase + (uint32_t)(c % 3) * STG;
        const uint32_t sB = sA + ABYTES;
        #pragma unroll
        for (int ks = 0; ks < 4; ks++) {
            uint32_t a[2][4];
            #pragma unroll
            for (int mi = 0; mi < 2; mi++) {
                uint32_t addr = sA +
                    (uint32_t)((wm * 32 + mi * 16 + (lane & 15)) * APAD + ks * 16 + 8 * (lane >> 4)) * 2;
                ldsm4(addr, a[mi][0], a[mi][1], a[mi][2], a[mi][3]);
            }
            #pragma unroll
            for (int ng = 0; ng < 2; ng++) {
                uint32_t b0, b1, b2, b3;
                uint32_t addr = sB +
                    (uint32_t)((ks * 16 + (lane & 15)) * BPAD + wn * 32 + ng * 16 + 8 * (lane >> 4)) * 2;
                ldsm4t(addr, b0, b1, b2, b3);
                mma_f16(acc[0][ng * 2],     a[0], b0, b1);
                mma_f16(acc[0][ng * 2 + 1], a[0], b2, b3);
                mma_f16(acc[1][ng * 2],     a[1], b0, b1);
                mma_f16(acc[1][ng * 2 + 1], a[1], b2, b3);
            }
        }
    }

    const int cbl = wn * 32 + (lane & 3) * 2;     // col within 64-wide block

    if (HEAD_FUSE) {
        // T = relu(acc + b1); out[row, head] = sum_col T * w2 + b2.  head = blockIdx.y.
        float part[2][2] = {{0.f, 0.f}, {0.f, 0.f}};   // [mi][h]
        #pragma unroll
        for (int mi = 0; mi < 2; mi++)
            #pragma unroll
            for (int ni = 0; ni < 4; ni++) {
                int col = col0 + cbl + ni * 8;
                float wA = w2cat[col], wB = w2cat[col + 1];
                float bA = bias[col], bB = bias[col + 1];
                #pragma unroll
                for (int h = 0; h < 2; h++) {
                    float v0 = fmaxf(acc[mi][ni][h * 2 + 0] + bA, 0.f);
                    float v1 = fmaxf(acc[mi][ni][h * 2 + 1] + bB, 0.f);
                    part[mi][h] = fmaf(v0, wA, fmaf(v1, wB, part[mi][h]));
                }
            }
        #pragma unroll
        for (int mi = 0; mi < 2; mi++)
            #pragma unroll
            for (int h = 0; h < 2; h++) {
                part[mi][h] += __shfl_xor_sync(0xffffffffu, part[mi][h], 1);
                part[mi][h] += __shfl_xor_sync(0xffffffffu, part[mi][h], 2);
            }
        float* red = (float*)sm;                   // reuse pipeline smem
        __syncthreads();
        if (wn == 0 && (lane & 3) == 0) {
            #pragma unroll
            for (int mi = 0; mi < 2; mi++)
                #pragma unroll
                for (int h = 0; h < 2; h++)
                    red[wm * 32 + (lane >> 2) + mi * 16 + h * 8] = part[mi][h];
        }
        __syncthreads();
        if (wn == 1 && (lane & 3) == 0) {
            float b2s = b2v[blockIdx.y];
            #pragma unroll
            for (int mi = 0; mi < 2; mi++)
                #pragma unroll
                for (int h = 0; h < 2; h++) {
                    int r = wm * 32 + (lane >> 2) + mi * 16 + h * 8;
                    int rg = row0 + r;
                    if (rg < n)
                        out1[(size_t)2 * rg + blockIdx.y] = red[r] + part[mi][h] + b2s;
                }
        }
        return;
    }

    // standard epilogue
    const int rb = row0 + wm * 32 + (lane >> 2);
    #pragma unroll
    for (int mi = 0; mi < 2; mi++) {
        #pragma unroll
        for (int ni = 0; ni < 4; ni++) {
            int col = col0 + cbl + ni * 8;        // global col within NT
            #pragma unroll
            for (int h = 0; h < 2; h++) {
                int rg = rb + mi * 16 + h * 8;
                if (rg < n) {
                    float2 v;
                    v.x = acc[mi][ni][h * 2 + 0];
                    v.y = acc[mi][ni][h * 2 + 1];
                    if (BIAS_RELU) {
                        v.x = fmaxf(v.x + bias[col], 0.f);
                        v.y = fmaxf(v.y + bias[col + 1], 0.f);
                    }
                    float* dst = out1;
                    int cc = col;
                    if (NT == 256 && col >= 128) { dst = out2; cc = col - 128; }
                    if (HALF_OUT) {
                        __half2 hv = __floats2half2_rn(v.x, v.y);
                        *(__half2*)((__half*)dst + (size_t)rg * 128 + cc) = hv;
                    } else {
                        *(float2*)(dst + (size_t)rg * 128 + cc) = v;
                    }
                }
            }
        }
    }
}

// ---------------- CSR build ----------------
__global__ void k_zero(int n) {
    int i = blockIdx.x * blockDim.x + threadIdx.x;
    if (i < n) g_cnt[i] = 0;
}

__global__ void k_count(const int* __restrict__ dstv, int e) {
    int i = blockIdx.x * blockDim.x + threadIdx.x;
    if (i < e) atomicAdd(&g_cnt[dstv[i]], 1);
}

__global__ void k_scan_a(int n) {
    __shared__ int sh[256];
    int i = blockIdx.x * 256 + threadIdx.x;
    int v = (i < n) ? g_cnt[i] : 0;
    sh[threadIdx.x] = v;
    __syncthreads();
    #pragma unroll
    for (int o = 1; o < 256; o <<= 1) {
        int t = (threadIdx.x >= o) ? sh[threadIdx.x - o] : 0;
        __syncthreads();
        sh[threadIdx.x] += t;
        __syncthreads();
    }
    if (i < n) g_row[i] = sh[threadIdx.x] - v;
    if (threadIdx.x == 255) g_bsum[blockIdx.x] = sh[255];
}

__global__ void k_scan_b(int nb) {
    __shared__ int sh[NB_MAX];
    int t = threadIdx.x;
    int v = (t < nb) ? g_bsum[t] : 0;
    sh[t] = v;
    __syncthreads();
    #pragma unroll
    for (int o = 1; o < NB_MAX; o <<= 1) {
        int u = (t >= o) ? sh[t - o] : 0;
        __syncthreads();
        sh[t] += u;
        __syncthreads();
    }
    if (t < nb) g_bsum[t] = sh[t] - v;
}

__global__ void k_scan_c(int n, int e) {
    int i = blockIdx.x * 256 + threadIdx.x;
    if (i < n) {
        int r = g_row[i] + g_bsum[blockIdx.x];
        g_row[i] = r;
        g_cur[i] = r;
    }
    if (i == 0) g_row[n] = e;
}

__global__ void k_scatter(const int* __restrict__ srcv, const int* __restrict__ dstv, int e) {
    int i = blockIdx.x * blockDim.x + threadIdx.x;
    if (i < e) {
        int pos = atomicAdd(&g_cur[dstv[i]], 1);
        g_csrc[pos] = srcv[i];
    }
}

__global__ void k_sortcsr(int n) {
    int i = blockIdx.x * blockDim.x + threadIdx.x;
    if (i >= n) return;
    int b = g_row[i], e2 = g_row[i + 1];
    for (int a = b + 1; a < e2; a++) {
        int v = g_csrc[a];
        int k = a;
        while (k > b && g_csrc[k - 1] > v) { g_csrc[k] = g_csrc[k - 1]; k--; }
        g_csrc[k] = v;
    }
}

// ---------------- LayerNorm kernels (write fp16 hi/lo pack for the GEMM) ----------------
__global__ void __launch_bounds__(256) k_ln64(const float* __restrict__ x,
                                              const float* __restrict__ g,
                                              const float* __restrict__ b,
                                              __half* __restrict__ pack, int n) {
    int w = (blockIdx.x * 256 + threadIdx.x) >> 5;
    int lane = threadIdx.x & 31;
    if (w >= n) return;
    float2 v = *(const float2*)(x + (size_t)w * 64 + lane * 2);
    float s = v.x + v.y;
    float q = v.x * v.x + v.y * v.y;
    #pragma unroll
    for (int o = 16; o; o >>= 1) {
        s += __shfl_xor_sync(0xffffffffu, s, o);
        q += __shfl_xor_sync(0xffffffffu, q, o);
    }
    float m  = s * (1.f / 64.f);
    float var = q * (1.f / 64.f) - m * m;
    float rs = rsqrtf(var + 1e-5f);
    float2 gg = *(const float2*)(g + lane * 2);
    float2 bb = *(const float2*)(b + lane * 2);
    float y0 = (v.x - m) * rs * gg.x + bb.x;
    float y1 = (v.y - m) * rs * gg.y + bb.y;
    __half h0 = __float2half(y0), h1 = __float2half(y1);
    __half l0 = __float2half(y0 - __half2float(h0));
    __half l1 = __float2half(y1 - __half2float(h1));
    uint32_t hw = ((uint32_t)__half_as_ushort(h1) << 16) | __half_as_ushort(h0);
    uint32_t lw = ((uint32_t)__half_as_ushort(l1) << 16) | __half_as_ushort(l0);
    *(uint32_t*)(pack + (size_t)w * 128 + lane * 2)      = hw;
    *(uint32_t*)(pack + (size_t)w * 128 + 64 + lane * 2) = lw;
}

// LayerNorm + residual(from old pack hi) + relu + repack.
__global__ void __launch_bounds__(256) k_ln128(const float* __restrict__ in,
                                               const float* __restrict__ g,
                                               const float* __restrict__ b,
                                               int useRes, float rscale, int doRelu,
                                               __half* __restrict__ pack, int n) {
    int w = (blockIdx.x * 256 + threadIdx.x) >> 5;
    int lane = threadIdx.x & 31;
    if (w >= n) return;
    int c0 = lane * 4;
    float4 res4 = make_float4(0.f, 0.f, 0.f, 0.f);
    if (useRes) res4 = ld_half4(pack + (size_t)w * 256 + c0);   // old hi-half = previous h
    float4 v = *(const float4*)(in + (size_t)w * 128 + c0);
    float s = v.x + v.y + v.z + v.w;
    float q = v.x * v.x + v.y * v.y + v.z * v.z + v.w * v.w;
    #pragma unroll
    for (int o = 16; o; o >>= 1) {
        s += __shfl_xor_sync(0xffffffffu, s, o);
        q += __shfl_xor_sync(0xffffffffu, q, o);
    }
    float m   = s * (1.f / 128.f);
    float var = q * (1.f / 128.f) - m * m;
    float rs  = rsqrtf(var + 1e-5f);
    float4 gg = *(const float4*)(g + c0);
    float4 bb = *(const float4*)(b + c0);
    float4 y;
    y.x = (v.x - m) * rs * gg.x + bb.x;
    y.y = (v.y - m) * rs * gg.y + bb.y;
    y.z = (v.z - m) * rs * gg.z + bb.z;
    y.w = (v.w - m) * rs * gg.w + bb.w;
    if (useRes) {
        y.x += rscale * res4.x; y.y += rscale * res4.y;
        y.z += rscale * res4.z; y.w += rscale * res4.w;
    }
    if (doRelu) {
        y.x = fmaxf(y.x, 0.f); y.y = fmaxf(y.y, 0.f);
        y.z = fmaxf(y.z, 0.f); y.w = fmaxf(y.w, 0.f);
    }
    uint2 hi, lo;
    split4h(y, hi, lo);
    *(uint2*)(pack + (size_t)w * 256 + c0)       = hi;
    *(uint2*)(pack + (size_t)w * 256 + 128 + c0) = lo;
}

// ---------------- GATv2 aggregation: fp16 inputs, warp per dst node, online softmax ----------------
__global__ void __launch_bounds__(256) k_agg(const __half* __restrict__ xl,
                                             const __half* __restrict__ xr,
                                             const float* __restrict__ att,
                                             float* __restrict__ out, int n, int grp) {
    int w = (blockIdx.x * 256 + threadIdx.x) >> 5;
    int lane = threadIdx.x & 31;
    if (w >= n) return;
    int c0 = lane * 4;
    float4 a4 = *(const float4*)(att + c0);
    float4 r4 = ld_half4(xr + (size_t)w * 128 + c0);
    int beg = g_row[w], deg = g_row[w + 1] - beg;
    float m = -1e30f, s = 0.f;
    float4 acc = make_float4(0.f, 0.f, 0.f, 0.f);

    auto logit = [&](float4 x) -> float {
        float e0 = x.x + r4.x, e1 = x.y + r4.y, e2 = x.z + r4.z, e3 = x.w + r4.w;
        e0 = (e0 > 0.f) ? e0 : 0.2f * e0;
        e1 = (e1 > 0.f) ? e1 : 0.2f * e1;
        e2 = (e2 > 0.f) ? e2 : 0.2f * e2;
        e3 = (e3 > 0.f) ? e3 : 0.2f * e3;
        return fmaf(a4.x, e0, fmaf(a4.y, e1, fmaf(a4.z, e2, a4.w * e3)));
    };

    int j = -1;                              // j == -1 is the self-loop
    for (; j + 1 < deg; j += 2) {
        int s0 = (j < 0) ? w : g_csrc[beg + j];
        int s1 = g_csrc[beg + j + 1];
        float4 x0 = ld_half4(xl + (size_t)s0 * 128 + c0);
        float4 x1 = ld_half4(xl + (size_t)s1 * 128 + c0);
        float p0 = logit(x0);
        float p1 = logit(x1);
        #pragma unroll
        for (int o = 1; o < 32; o <<= 1)
            if (o < grp) {
                p0 += __shfl_xor_sync(0xffffffffu, p0, o);
                p1 += __shfl_xor_sync(0xffffffffu, p1, o);
            }
        float mn = fmaxf(m, fmaxf(p0, p1));
        float sc = __expf(m - mn);
        float w0 = __expf(p0 - mn);
        float w1 = __expf(p1 - mn);
        s = fmaf(s, sc, w0 + w1);
        acc.x = fmaf(acc.x, sc, fmaf(w0, x0.x, w1 * x1.x));
        acc.y = fmaf(acc.y, sc, fmaf(w0, x0.y, w1 * x1.y));
        acc.z = fmaf(acc.z, sc, fmaf(w0, x0.z, w1 * x1.z));
        acc.w = fmaf(acc.w, sc, fmaf(w0, x0.w, w1 * x1.w));
        m = mn;
    }
    if (j < deg) {                           // leftover single edge (or lone self-loop)
        int s0 = (j < 0) ? w : g_csrc[beg + j];
        float4 x0 = ld_half4(xl + (size_t)s0 * 128 + c0);
        float p0 = logit(x0);
        #pragma unroll
        for (int o = 1; o < 32; o <<= 1)
            if (o < grp) p0 += __shfl_xor_sync(0xffffffffu, p0, o);
        float mn = fmaxf(m, p0);
        float sc = __expf(m - mn);
        float w0 = __expf(p0 - mn);
        s = fmaf(s, sc, w0);
        acc.x = fmaf(acc.x, sc, w0 * x0.x);
        acc.y = fmaf(acc.y, sc, w0 * x0.y);
        acc.z = fmaf(acc.z, sc, w0 * x0.z);
        acc.w = fmaf(acc.w, sc, w0 * x0.w);
        m = mn;
    }
    float inv = 1.f / s;
    float4 o4 = make_float4(acc.x * inv, acc.y * inv, acc.z * inv, acc.w * inv);
    *(float4*)(out + (size_t)w * 128 + c0) = o4;
}

// ---------------- launch ----------------
extern "C" void kernel_launch(void* const* d_in, const int* in_sizes, int n_in,
                              void* d_out, int out_size) {
    const float* x       = (const float*)d_in[0];
    const int*   ei      = (const int*)  d_in[1];
    const float* ln_in_g = (const float*)d_in[2];
    const float* ln_in_b = (const float*)d_in[3];
    const float* w_l1    = (const float*)d_in[4];
    const float* w_r1    = (const float*)d_in[5];
    const float* att1    = (const float*)d_in[6];
    const float* ln1_g   = (const float*)d_in[7];
    const float* ln1_b   = (const float*)d_in[8];
    const float* w_l2    = (const float*)d_in[9];
    const float* w_r2    = (const float*)d_in[10];
    const float* att2    = (const float*)d_in[11];
    const float* ln2_g   = (const float*)d_in[12];
    const float* ln2_b   = (const float*)d_in[13];
    const float* w_l3    = (const float*)d_in[14];
    const float* w_r3    = (const float*)d_in[15];
    const float* att3    = (const float*)d_in[16];
    const float* ln3_g   = (const float*)d_in[17];
    const float* ln3_b   = (const float*)d_in[18];
    const float* rtt_w1  = (const float*)d_in[19];
    const float* rtt_b1  = (const float*)d_in[20];
    const float* rtt_w2  = (const float*)d_in[21];
    const float* rtt_b2  = (const float*)d_in[22];
    const float* ret_w1  = (const float*)d_in[23];
    const float* ret_b1  = (const float*)d_in[24];
    const float* ret_w2  = (const float*)d_in[25];
    const float* ret_b2  = (const float*)d_in[26];

    const int n = in_sizes[0] / 64;
    const int e = in_sizes[1] / 2;
    const int* srcv = ei;
    const int* dstv = ei + e;

    float *p_xl, *p_xr, *p_gg, *p_b1, *p_w2, *p_b2;
    __half *p_pk, *p_W0, *p_W1, *p_W2, *p_WH;
    cudaGetSymbolAddress((void**)&p_xl, g_xl);
    cudaGetSymbolAddress((void**)&p_xr, g_xr);
    cudaGetSymbolAddress((void**)&p_gg, g_gg);
    cudaGetSymbolAddress((void**)&p_b1, g_b1cat);
    cudaGetSymbolAddress((void**)&p_w2, g_w2cat);
    cudaGetSymbolAddress((void**)&p_b2, g_b2);
    cudaGetSymbolAddress((void**)&p_pk, g_pk);
    cudaGetSymbolAddress((void**)&p_W0, g_W0);
    cudaGetSymbolAddress((void**)&p_W1, g_W1);
    cudaGetSymbolAddress((void**)&p_W2, g_W2);
    cudaGetSymbolAddress((void**)&p_WH, g_WH);
    __half* h_xl = (__half*)p_xl;
    __half* h_xr = (__half*)p_xr;

    const int NBn = (n + 255) / 256;
    const int EB  = (e + 255) / 256;
    const int WB  = (n + 7) / 8;
    const int GBx = (n + 127) / 128;
    dim3 GB256(GBx, 4);   // NT=256 -> 4 column blocks of 64
    dim3 GB128(GBx, 2);   // NT=128 -> 2 column blocks of 64 (heads: y = head index)

    const int SMEM = 3 * (128 * APAD * 2 + 64 * BPAD * 2);   // 82944
    cudaFuncSetAttribute((const void*)k_gemm_mma<64, 256, false, true, false>,
                         cudaFuncAttributeMaxDynamicSharedMemorySize, SMEM);
    cudaFuncSetAttribute((const void*)k_gemm_mma<128, 256, false, true, false>,
                         cudaFuncAttributeMaxDynamicSharedMemorySize, SMEM);
    cudaFuncSetAttribute((const void*)k_gemm_mma<128, 128, true, false, true>,
                         cudaFuncAttributeMaxDynamicSharedMemorySize, SMEM);

    cudaStream_t s2;
    cudaEvent_t evFork, evCSR, evW2;
    cudaStreamCreateWithFlags(&s2, cudaStreamNonBlocking);
    cudaEventCreateWithFlags(&evFork, cudaEventDisableTiming);
    cudaEventCreateWithFlags(&evCSR, cudaEventDisableTiming);
    cudaEventCreateWithFlags(&evW2, cudaEventDisableTiming);

    // --- main branch: minimal prologue before gemm0 ---
    k_ln64<<<WB, 256>>>(x, ln_in_g, ln_in_b, p_pk, n);
    k_convW<64, 256> <<<(64 * 256 + 255) / 256, 256>>>(w_l1, w_r1, p_W0);
    k_convW<128, 256><<<(128 * 256 + 255) / 256, 256>>>(w_l2, w_r2, p_W1);
    k_gemm_mma<64, 256, false, true, false><<<GB256, 256, SMEM>>>(
        p_pk, p_W0, p_xl, p_xr, nullptr, nullptr, nullptr, n);

    // --- side branch: CSR build + late weight conversions ---
    cudaEventRecord(evFork, 0);
    cudaStreamWaitEvent(s2, evFork, 0);
    k_zero   <<<NBn, 256, 0, s2>>>(n);
    k_count  <<<EB,  256, 0, s2>>>(dstv, e);
    k_scan_a <<<NBn, 256, 0, s2>>>(n);
    k_scan_b <<<1, NB_MAX, 0, s2>>>(NBn);
    k_scan_c <<<NBn, 256, 0, s2>>>(n, e);
    k_scatter<<<EB,  256, 0, s2>>>(srcv, dstv, e);
    k_sortcsr<<<NBn, 256, 0, s2>>>(n);
    cudaEventRecord(evCSR, s2);
    k_convW<128, 256><<<(128 * 256 + 255) / 256, 256, 0, s2>>>(w_l3, w_r3, p_W2);
    k_convW<128, 128><<<(128 * 128 + 255) / 256, 256, 0, s2>>>(rtt_w1, ret_w1, p_WH);
    k_biascat<<<1, 128, 0, s2>>>(rtt_b1, ret_b1, rtt_w2, ret_w2, rtt_b2, ret_b2);
    cudaEventRecord(evW2, s2);

    // --- layer 0 aggregation (needs CSR) ---
    cudaStreamWaitEvent(0, evCSR, 0);
    k_agg<<<WB, 256>>>(h_xl, h_xr, att1, p_gg, n, 8);
    k_ln128<<<WB, 256>>>(p_gg, ln1_g, ln1_b, 0, 0.f, 1, p_pk, n);

    // --- layer 1 (residual = old pack hi) ---
    k_gemm_mma<128, 256, false, true, false><<<GB256, 256, SMEM>>>(
        p_pk, p_W1, p_xl, p_xr, nullptr, nullptr, nullptr, n);
    k_agg<<<WB, 256>>>(h_xl, h_xr, att2, p_gg, n, 8);
    k_ln128<<<WB, 256>>>(p_gg, ln2_g, ln2_b, 1, 0.1f, 1, p_pk, n);

    // --- layer 2 (needs W2 from side stream; residual = old pack hi) ---
    cudaStreamWaitEvent(0, evW2, 0);
    k_gemm_mma<128, 256, false, true, false><<<GB256, 256, SMEM>>>(
        p_pk, p_W2, p_xl, p_xr, nullptr, nullptr, nullptr, n);
    k_agg<<<WB, 256>>>(h_xl, h_xr, att3, p_gg, n, 32);
    k_ln128<<<WB, 256>>>(p_gg, ln3_g, ln3_b, 1, 0.1f, 0, p_pk, n);

    // --- heads: fused GEMM + w2 dot, 2-term precision, writes d_out directly ---
    k_gemm_mma<128, 128, true, false, true><<<GB128, 256, SMEM>>>(
        p_pk, p_WH, (float*)d_out, nullptr, p_b1, p_w2, p_b2, n);
}